// round 5
// baseline (speedup 1.0000x reference)
#include <cuda_runtime.h>
#include <math.h>
#include <stddef.h>

#define Nh   1024
#define LSEQ 16384
#define NT1  512
#define NT2  32

// ---------------- static device scratch ----------------
__device__ float g_S[Nh*Nh];
__device__ float g_T[Nh*Nh];
__device__ float g_P[Nh*Nh];
__device__ float g_M[Nh*Nh];
__device__ float g_U[NT1*Nh];
__device__ float g_W[NT2*Nh];
__device__ float g_K[LSEQ];

// ---------------- elementwise ----------------
__global__ void k_prep(const float* __restrict__ A, const float* __restrict__ logd,
                       float* __restrict__ S) {
    int i = blockIdx.x*blockDim.x + threadIdx.x;
    float d = (float)exp((double)logd[0]);
    S[i] = 0.5f*d*A[i];
}
__global__ void k_copy(const float* __restrict__ src, float* __restrict__ dst, int n) {
    int i = blockIdx.x*blockDim.x + threadIdx.x;
    if (i < n) dst[i] = src[i];
}

// ---------------- GEMM: 64x64 tile, BK=16, 128 thr, 8Mx4N micro (f32x2),
// ---------------- B duplicated in smem, double-buffered -----------------
#define BM 64
#define BN 64
#define BK 16
#define NTHR 128

#define MODE_PLAIN 0
#define MODE_P0    1   // C = I + E + A@B
#define MODE_R     2   // C = 2I - E + A@B
#define MODE_PM    3   // C = A@B ; C2 = 2*(A@B) - I

template<int MODE>
__device__ __forceinline__ void gemm_tile(const float* __restrict__ A,
                                          const float* __restrict__ B,
                                          float* __restrict__ C,
                                          const float* __restrict__ E,
                                          float* __restrict__ C2,
                                          int Mrows, int bm, int bn) {
    __shared__ float As[2][BK][BM];        // transposed: As[buf][k][m]   (8 KB)
    __shared__ float Bs[2][BK][2*BN];      // duplicated pairs            (16 KB)
    const int tid = threadIdx.x;
    const int tx = tid & 15;               // out col group: n = tx*4 + j
    const int ty = tid >> 4;               // out row group: m = ty*8 + r

    // global-load mapping: 2 float4 per thread per buffer for each of A,B
    const int a_r0  = tid >> 2;            // + l*32 ; rows 0..63
    const int a_c4  = (tid & 3) << 2;      // k-quad within row
    const int b_r0  = tid >> 4;            // + l*8  ; k rows 0..15
    const int b_c4  = (tid & 15) << 2;     // col quad

    unsigned long long acc[4][4];
    #pragma unroll
    for (int p = 0; p < 4; p++)
        #pragma unroll
        for (int j = 0; j < 4; j++) acc[p][j] = 0ULL;

    float4 va[2], vb[2];

    // ---- prologue: load tile 0 ----
    #pragma unroll
    for (int l = 0; l < 2; l++) {
        int r = a_r0 + l*32;
        va[l] = make_float4(0.f,0.f,0.f,0.f);
        if (bm + r < Mrows) va[l] = *(const float4*)(A + (size_t)(bm + r)*Nh + a_c4);
        vb[l] = *(const float4*)(B + (size_t)(b_r0 + l*8)*Nh + bn + b_c4);
    }
    #pragma unroll
    for (int l = 0; l < 2; l++) {
        int r = a_r0 + l*32;
        As[0][a_c4+0][r] = va[l].x; As[0][a_c4+1][r] = va[l].y;
        As[0][a_c4+2][r] = va[l].z; As[0][a_c4+3][r] = va[l].w;
        int kr = b_r0 + l*8;
        *(float4*)(&Bs[0][kr][b_c4*2    ]) = make_float4(vb[l].x, vb[l].x, vb[l].y, vb[l].y);
        *(float4*)(&Bs[0][kr][b_c4*2 + 4]) = make_float4(vb[l].z, vb[l].z, vb[l].w, vb[l].w);
    }
    __syncthreads();

    const int ntiles = Nh / BK;   // 64
    int buf = 0;
    for (int t = 0; t < ntiles; t++) {
        if (t + 1 < ntiles) {
            int kt = (t + 1) * BK;
            #pragma unroll
            for (int l = 0; l < 2; l++) {
                int r = a_r0 + l*32;
                va[l] = make_float4(0.f,0.f,0.f,0.f);
                if (bm + r < Mrows) va[l] = *(const float4*)(A + (size_t)(bm + r)*Nh + kt + a_c4);
                vb[l] = *(const float4*)(B + (size_t)(kt + b_r0 + l*8)*Nh + bn + b_c4);
            }
        }
        #pragma unroll
        for (int k = 0; k < BK; k++) {
            ulonglong2 a01 = *(const ulonglong2*)(&As[buf][k][ty*8]);
            ulonglong2 a23 = *(const ulonglong2*)(&As[buf][k][ty*8 + 4]);
            ulonglong2 b01 = *(const ulonglong2*)(&Bs[buf][k][tx*8]);
            ulonglong2 b23 = *(const ulonglong2*)(&Bs[buf][k][tx*8 + 4]);
            unsigned long long a[4] = {a01.x, a01.y, a23.x, a23.y};
            unsigned long long b[4] = {b01.x, b01.y, b23.x, b23.y};
            #pragma unroll
            for (int p = 0; p < 4; p++)
                #pragma unroll
                for (int j = 0; j < 4; j++)
                    asm("fma.rn.f32x2 %0, %1, %2, %0;"
                        : "+l"(acc[p][j]) : "l"(a[p]), "l"(b[j]));
        }
        if (t + 1 < ntiles) {
            int nbuf = buf ^ 1;
            #pragma unroll
            for (int l = 0; l < 2; l++) {
                int r = a_r0 + l*32;
                As[nbuf][a_c4+0][r] = va[l].x; As[nbuf][a_c4+1][r] = va[l].y;
                As[nbuf][a_c4+2][r] = va[l].z; As[nbuf][a_c4+3][r] = va[l].w;
                int kr = b_r0 + l*8;
                *(float4*)(&Bs[nbuf][kr][b_c4*2    ]) = make_float4(vb[l].x, vb[l].x, vb[l].y, vb[l].y);
                *(float4*)(&Bs[nbuf][kr][b_c4*2 + 4]) = make_float4(vb[l].z, vb[l].z, vb[l].w, vb[l].w);
            }
        }
        __syncthreads();
        buf ^= 1;
    }

    // ---- epilogue ----
    #pragma unroll
    for (int p = 0; p < 4; p++) {
        float4 lo, hi;
        lo.x = __uint_as_float((unsigned)(acc[p][0]));  hi.x = __uint_as_float((unsigned)(acc[p][0] >> 32));
        lo.y = __uint_as_float((unsigned)(acc[p][1]));  hi.y = __uint_as_float((unsigned)(acc[p][1] >> 32));
        lo.z = __uint_as_float((unsigned)(acc[p][2]));  hi.z = __uint_as_float((unsigned)(acc[p][2] >> 32));
        lo.w = __uint_as_float((unsigned)(acc[p][3]));  hi.w = __uint_as_float((unsigned)(acc[p][3] >> 32));
        #pragma unroll
        for (int h = 0; h < 2; h++) {
            int m  = bm + ty*8 + 2*p + h;
            int n0 = bn + tx*4;
            float4 v = h ? hi : lo;
            if (MODE == MODE_P0 || MODE == MODE_R) {
                float4 e = *(const float4*)(E + (size_t)m*Nh + n0);
                if (MODE == MODE_P0) {
                    v.x += e.x; v.y += e.y; v.z += e.z; v.w += e.w;
                    if (m == n0)   v.x += 1.f; if (m == n0+1) v.y += 1.f;
                    if (m == n0+2) v.z += 1.f; if (m == n0+3) v.w += 1.f;
                } else {
                    v.x -= e.x; v.y -= e.y; v.z -= e.z; v.w -= e.w;
                    if (m == n0)   v.x += 2.f; if (m == n0+1) v.y += 2.f;
                    if (m == n0+2) v.z += 2.f; if (m == n0+3) v.w += 2.f;
                }
            }
            if (MODE == MODE_PLAIN) {
                if (m < Mrows) *(float4*)(C + (size_t)m*Nh + n0) = v;
            } else {
                *(float4*)(C + (size_t)m*Nh + n0) = v;
            }
            if (MODE == MODE_PM) {
                float4 w;
                w.x = 2.f*v.x; w.y = 2.f*v.y; w.z = 2.f*v.z; w.w = 2.f*v.w;
                if (m == n0)   w.x -= 1.f; if (m == n0+1) w.y -= 1.f;
                if (m == n0+2) w.z -= 1.f; if (m == n0+3) w.w -= 1.f;
                *(float4*)(C2 + (size_t)m*Nh + n0) = w;
            }
        }
    }
}

template<int MODE>
__global__ __launch_bounds__(NTHR)
void k_gemm(const float* __restrict__ A, const float* __restrict__ B,
            float* __restrict__ C, const float* __restrict__ E,
            float* __restrict__ C2, int Mrows) {
    gemm_tile<MODE>(A, B, C, E, C2, Mrows, blockIdx.y*BM, blockIdx.x*BN);
}

// Fused doubling step: y<16 -> squaring Psq = Pw@Pw ; y>=16 -> U-ext = U[0..rows)@Pw
__global__ __launch_bounds__(NTHR)
void k_step(const float* __restrict__ U, const float* __restrict__ Pw,
            float* __restrict__ Unext, int rows, float* __restrict__ Psq) {
    int by = blockIdx.y;
    if (by < 16)
        gemm_tile<MODE_PLAIN>(Pw, Pw, Psq, nullptr, nullptr, Nh, by*BM, blockIdx.x*BN);
    else
        gemm_tile<MODE_PLAIN>(U, Pw, Unext, nullptr, nullptr, rows, (by - 16)*BM, blockIdx.x*BN);
}

// ---------------- matvec: y = Mat @ x, optional scale exp(logd) ----------------
__global__ void k_matvec(const float* __restrict__ Mat, const float* __restrict__ x,
                         float* __restrict__ y, const float* __restrict__ logd) {
    int gw   = (blockIdx.x*blockDim.x + threadIdx.x) >> 5;
    int lane = threadIdx.x & 31;
    if (gw >= Nh) return;
    const float4* r  = (const float4*)(Mat + (size_t)gw*Nh);
    const float4* xv = (const float4*)x;
    float acc = 0.f;
    #pragma unroll 4
    for (int j = lane; j < Nh/4; j += 32) {
        float4 a = r[j], b = xv[j];
        acc += a.x*b.x + a.y*b.y + a.z*b.z + a.w*b.w;
    }
    #pragma unroll
    for (int o = 16; o; o >>= 1) acc += __shfl_down_sync(0xffffffffu, acc, o);
    if (lane == 0) {
        float s = 1.f;
        if (logd) s = (float)exp((double)logd[0]);
        y[gw] = s*acc;
    }
}

// ---------------- K[t1 + 512*t2] = dot(U[t1,:], W[t2,:]) ----------------
__global__ void k_gk(const float* __restrict__ U, const float* __restrict__ W,
                     float* __restrict__ K) {
    int gw   = (blockIdx.x*blockDim.x + threadIdx.x) >> 5;
    int lane = threadIdx.x & 31;
    if (gw >= LSEQ) return;
    int t1 = gw & (NT1 - 1);
    int t2 = gw >> 9;
    const float4* u = (const float4*)(U + (size_t)t1*Nh);
    const float4* w = (const float4*)(W + (size_t)t2*Nh);
    float acc = 0.f;
    #pragma unroll 4
    for (int j = lane; j < Nh/4; j += 32) {
        float4 a = u[j], b = w[j];
        acc += a.x*b.x + a.y*b.y + a.z*b.z + a.w*b.w;
    }
    #pragma unroll
    for (int o = 16; o; o >>= 1) acc += __shfl_down_sync(0xffffffffu, acc, o);
    if (lane == 0) K[gw] = acc;
}

// ---------------- causal conv: Y[k] = sum_{t<=k} K[t] X[k-t] + D*X[k] ----------------
__global__ __launch_bounds__(128)
void k_conv(const float* __restrict__ X, const float* __restrict__ K,
            const float* __restrict__ D, float* __restrict__ Y) {
    __shared__ float Ks[256];
    __shared__ float Xs[128];
    const int i  = blockIdx.x;
    const int kk = threadIdx.x;
    float acc = 0.f;
    for (int j = 0; j <= i; j++) {
        int base = (i - j) << 7;
        __syncthreads();
        Xs[kk] = X[(j << 7) + kk];
        int i0 = base - 128 + kk;
        Ks[kk]       = (i0 >= 0) ? K[i0] : 0.f;
        Ks[kk + 128] = K[base + kk];
        __syncthreads();
        #pragma unroll 8
        for (int t = 0; t < 128; t++)
            acc += Ks[kk + 128 - t] * Xs[t];
    }
    int k = (i << 7) + kk;
    Y[k] = acc + D[0]*X[k];
}

// ---------------- host ----------------
extern "C" void kernel_launch(void* const* d_in, const int* in_sizes, int n_in,
                              void* d_out, int out_size) {
    int iX=-1, iA=-1, iB=-1, iC=-1, iD=-1, iLd=-1;
    for (int i = 0; i < n_in; i++) {
        int s = in_sizes[i];
        if      (s == Nh*Nh) iA = i;
        else if (s == LSEQ)  iX = i;
        else if (s == Nh)    { if (iB < 0) iB = i; else iC = i; }
        else if (s == 1)     { if (iD < 0) iD = i; else iLd = i; }
    }
    const float* X    = (const float*)d_in[iX];
    const float* A    = (const float*)d_in[iA];
    const float* Bv   = (const float*)d_in[iB];
    const float* Cv   = (const float*)d_in[iC];
    const float* Dv   = (const float*)d_in[iD];
    const float* logd = (const float*)d_in[iLd];
    float* Y = (float*)d_out;
    (void)out_size;

    float *pS, *pT, *pP, *pM, *pU, *pW, *pK;
    cudaGetSymbolAddress((void**)&pS, g_S);
    cudaGetSymbolAddress((void**)&pT, g_T);
    cudaGetSymbolAddress((void**)&pP, g_P);
    cudaGetSymbolAddress((void**)&pM, g_M);
    cudaGetSymbolAddress((void**)&pU, g_U);
    cudaGetSymbolAddress((void**)&pW, g_W);
    cudaGetSymbolAddress((void**)&pK, g_K);

    const int EW = (Nh*Nh)/256;
    dim3 g2(Nh/BN, Nh/BM);   // 16 x 16

    // S = (d/2) A   -> g_S
    k_prep<<<EW, 256>>>(A, logd, pS);
    // P0 = I + S + S^2                      -> g_P
    k_gemm<MODE_P0><<<g2, NTHR>>>(pS, pS, pP, pS, nullptr, Nh);
    // R  = 2I - P0 + S@P0                   -> g_T
    k_gemm<MODE_R ><<<g2, NTHR>>>(pS, pP, pT, pP, nullptr, Nh);
    // P  = P0@R -> g_S ;  M = 2P - I -> g_M
    k_gemm<MODE_PM><<<g2, NTHR>>>(pP, pT, pS, nullptr, pM, Nh);

    k_matvec<<<128, 256>>>(pS, Bv, pW, logd);      // W[0] = dB = d * P @ B
    k_copy<<<4, 256>>>(Cv, pU, Nh);                // U[0] = c

    // Fused doubling: U[rows..2rows) = U @ M^{2^s}, M^{2^{s+1}} = (M^{2^s})^2
    float* pw   = pM;
    float* ping = pP;
    float* pong = pT;
    int rows = 1;
    for (int s = 0; s < 9; s++) {
        int urt = (rows + BM - 1)/BM;
        dim3 gs(Nh/BN, 16 + urt);
        k_step<<<gs, NTHR>>>(pU, pw, pU + (size_t)rows*Nh, rows, ping);
        pw = ping;
        float* tmp = ping; ping = pong; pong = tmp;
        rows <<= 1;
    }
    // pw = M^512

    // W[t] = M^512 @ W[t-1]
    for (int t = 1; t < NT2; t++)
        k_matvec<<<128, 256>>>(pw, pW + (size_t)(t-1)*Nh, pW + (size_t)t*Nh, nullptr);

    // K[t1 + 512*t2] = U[t1] . W[t2]
    k_gk<<<LSEQ/8, 256>>>(pU, pW, pK);

    // y = K (*) X + D*X
    k_conv<<<LSEQ/128, 128>>>(X, pK, Dv, Y);
}

// round 7
// speedup vs baseline: 1.3659x; 1.3659x over previous
#include <cuda_runtime.h>
#include <math.h>
#include <stddef.h>

#define Nh   1024
#define LSEQ 16384
#define NT1  512
#define NT2  32

// ---------------- static device scratch ----------------
__device__ float g_S[Nh*Nh];
__device__ float g_T[Nh*Nh];
__device__ float g_P[Nh*Nh];
__device__ float g_M[Nh*Nh];
__device__ float g_U[NT1*Nh];
__device__ float g_W[NT2*Nh];
__device__ float g_K[LSEQ];

// ---------------- helpers ----------------
__device__ __forceinline__ unsigned smem_u32(const void* p) {
    return (unsigned)__cvta_generic_to_shared(p);
}
__device__ __forceinline__ void cp16(unsigned dst, const void* src) {
    asm volatile("cp.async.cg.shared.global [%0], [%1], 16;\n" :: "r"(dst), "l"(src));
}
__device__ __forceinline__ void ffma2(unsigned long long& acc,
                                      unsigned long long a, unsigned long long b) {
    asm("fma.rn.f32x2 %0, %1, %2, %0;" : "+l"(acc) : "l"(a), "l"(b));
}
__device__ __forceinline__ unsigned long long dupf(float x) {
    unsigned long long r; unsigned u = __float_as_uint(x);
    asm("mov.b64 %0,{%1,%1};" : "=l"(r) : "r"(u));
    return r;
}

// ---------------- elementwise ----------------
__global__ void k_prep(const float* __restrict__ A, const float* __restrict__ logd,
                       float* __restrict__ S) {
    int i = blockIdx.x*blockDim.x + threadIdx.x;
    float d = (float)exp((double)logd[0]);
    S[i] = 0.5f*d*A[i];
}
__global__ void k_copy(const float* __restrict__ src, float* __restrict__ dst, int n) {
    int i = blockIdx.x*blockDim.x + threadIdx.x;
    if (i < n) dst[i] = src[i];
}

// ---------------- GEMM: 128x64 tile, BK=16, 128 thr, 8x8 micro (f32x2) ----
// A reg-staged + transposed into smem; B via cp.async; double-buffered.
#define BM 128
#define BN 64
#define BK 16
#define NTHR 128

#define MODE_PLAIN 0
#define MODE_P0    1   // C = I + E + A@B
#define MODE_R     2   // C = 2I - E + A@B
#define MODE_PM    3   // C = A@B ; C2 = 2*(A@B) - I

template<int MODE>
__device__ __forceinline__ void gemm_tile(const float* __restrict__ A,
                                          const float* __restrict__ B,
                                          float* __restrict__ C,
                                          const float* __restrict__ E,
                                          float* __restrict__ C2,
                                          int Mrows, int bm, int bn) {
    __shared__ __align__(16) float As[2][BK][BM];   // 16 KB, transposed As[b][k][m]
    __shared__ __align__(16) float Bs[2][BK][BN];   // 8 KB
    const int tid = threadIdx.x;
    const int tx = tid & 7;          // n0 = tx*8
    const int ty = tid >> 3;         // m0 = ty*8

    unsigned long long acc[4][8];
    #pragma unroll
    for (int p = 0; p < 4; p++)
        #pragma unroll
        for (int j = 0; j < 8; j++) acc[p][j] = 0ULL;

    const bool arow_ok = (bm + tid) < Mrows;
    const float* arow = A + (size_t)(bm + tid)*Nh;
    const unsigned bs_addr[2] = { smem_u32(&Bs[0][0][0]), smem_u32(&Bs[1][0][0]) };
    const int brow = tid >> 4;             // base k-row; second slot at +8
    const int bq4  = (tid & 15) << 2;      // col quad

    float4 areg[4];
    // ---- prologue: tile 0 ----
    #pragma unroll
    for (int q = 0; q < 4; q++)
        areg[q] = arow_ok ? *(const float4*)(arow + q*4) : make_float4(0.f,0.f,0.f,0.f);
    #pragma unroll
    for (int l = 0; l < 2; l++) {
        int r = brow + l*8;
        cp16(bs_addr[0] + (unsigned)(r*BN + bq4)*4, B + (size_t)r*Nh + bn + bq4);
    }
    asm volatile("cp.async.commit_group;\n" ::: "memory");
    #pragma unroll
    for (int q = 0; q < 4; q++) {
        As[0][q*4+0][tid] = areg[q].x; As[0][q*4+1][tid] = areg[q].y;
        As[0][q*4+2][tid] = areg[q].z; As[0][q*4+3][tid] = areg[q].w;
    }
    asm volatile("cp.async.wait_group 0;\n" ::: "memory");
    __syncthreads();

    const int ntiles = Nh / BK;   // 64
    int buf = 0;
    for (int t = 0; t < ntiles; t++) {
        if (t + 1 < ntiles) {
            int kt = (t + 1)*BK;
            #pragma unroll
            for (int q = 0; q < 4; q++)
                areg[q] = arow_ok ? *(const float4*)(arow + kt + q*4)
                                  : make_float4(0.f,0.f,0.f,0.f);
            unsigned bsn = bs_addr[buf ^ 1];
            #pragma unroll
            for (int l = 0; l < 2; l++) {
                int r = brow + l*8;
                cp16(bsn + (unsigned)(r*BN + bq4)*4, B + (size_t)(kt + r)*Nh + bn + bq4);
            }
            asm volatile("cp.async.commit_group;\n" ::: "memory");
        }
        #pragma unroll
        for (int k = 0; k < BK; k++) {
            ulonglong2 a01 = *(const ulonglong2*)(&As[buf][k][ty*8]);
            ulonglong2 a23 = *(const ulonglong2*)(&As[buf][k][ty*8 + 4]);
            float4 b0 = *(const float4*)(&Bs[buf][k][tx*8]);
            float4 b1 = *(const float4*)(&Bs[buf][k][tx*8 + 4]);
            unsigned long long a[4] = {a01.x, a01.y, a23.x, a23.y};
            unsigned long long bb[8] = {dupf(b0.x), dupf(b0.y), dupf(b0.z), dupf(b0.w),
                                        dupf(b1.x), dupf(b1.y), dupf(b1.z), dupf(b1.w)};
            #pragma unroll
            for (int p = 0; p < 4; p++)
                #pragma unroll
                for (int j = 0; j < 8; j++)
                    ffma2(acc[p][j], a[p], bb[j]);
        }
        if (t + 1 < ntiles) {
            int nb = buf ^ 1;
            #pragma unroll
            for (int q = 0; q < 4; q++) {
                As[nb][q*4+0][tid] = areg[q].x; As[nb][q*4+1][tid] = areg[q].y;
                As[nb][q*4+2][tid] = areg[q].z; As[nb][q*4+3][tid] = areg[q].w;
            }
            asm volatile("cp.async.wait_group 0;\n" ::: "memory");
        }
        __syncthreads();
        buf ^= 1;
    }

    // ---- epilogue ----
    #pragma unroll
    for (int p = 0; p < 4; p++) {
        float lo[8], hi[8];
        #pragma unroll
        for (int j = 0; j < 8; j++) {
            lo[j] = __uint_as_float((unsigned)(acc[p][j]));
            hi[j] = __uint_as_float((unsigned)(acc[p][j] >> 32));
        }
        #pragma unroll
        for (int h = 0; h < 2; h++) {
            int m  = bm + ty*8 + 2*p + h;
            int n0 = bn + tx*8;
            float* vr = h ? hi : lo;
            #pragma unroll
            for (int g = 0; g < 2; g++) {
                int nc = n0 + g*4;
                float4 v = make_float4(vr[g*4], vr[g*4+1], vr[g*4+2], vr[g*4+3]);
                if (MODE == MODE_P0 || MODE == MODE_R) {
                    float4 e = *(const float4*)(E + (size_t)m*Nh + nc);
                    if (MODE == MODE_P0) {
                        v.x += e.x; v.y += e.y; v.z += e.z; v.w += e.w;
                        if (m == nc)   v.x += 1.f; if (m == nc+1) v.y += 1.f;
                        if (m == nc+2) v.z += 1.f; if (m == nc+3) v.w += 1.f;
                    } else {
                        v.x -= e.x; v.y -= e.y; v.z -= e.z; v.w -= e.w;
                        if (m == nc)   v.x += 2.f; if (m == nc+1) v.y += 2.f;
                        if (m == nc+2) v.z += 2.f; if (m == nc+3) v.w += 2.f;
                    }
                }
                if (MODE == MODE_PLAIN) {
                    if (m < Mrows) *(float4*)(C + (size_t)m*Nh + nc) = v;
                } else {
                    *(float4*)(C + (size_t)m*Nh + nc) = v;
                }
                if (MODE == MODE_PM) {
                    float4 w;
                    w.x = 2.f*v.x; w.y = 2.f*v.y; w.z = 2.f*v.z; w.w = 2.f*v.w;
                    if (m == nc)   w.x -= 1.f; if (m == nc+1) w.y -= 1.f;
                    if (m == nc+2) w.z -= 1.f; if (m == nc+3) w.w -= 1.f;
                    *(float4*)(C2 + (size_t)m*Nh + nc) = w;
                }
            }
        }
    }
}

template<int MODE>
__global__ __launch_bounds__(NTHR)
void k_gemm(const float* __restrict__ A, const float* __restrict__ B,
            float* __restrict__ C, const float* __restrict__ E,
            float* __restrict__ C2, int Mrows) {
    gemm_tile<MODE>(A, B, C, E, C2, Mrows, blockIdx.y*BM, blockIdx.x*BN);
}

// Fused doubling: y<8 -> Psq = Pw@Pw ; y>=8 -> Unext = U[0..rows)@Pw
__global__ __launch_bounds__(NTHR)
void k_step(const float* __restrict__ U, const float* __restrict__ Pw,
            float* __restrict__ Unext, int rows, float* __restrict__ Psq) {
    int by = blockIdx.y;
    if (by < 8)
        gemm_tile<MODE_PLAIN>(Pw, Pw, Psq, nullptr, nullptr, Nh, by*BM, blockIdx.x*BN);
    else
        gemm_tile<MODE_PLAIN>(U, Pw, Unext, nullptr, nullptr, rows, (by - 8)*BM, blockIdx.x*BN);
}

// ---------------- matvec: y = Mat @ x, optional scale exp(logd) ----------------
__global__ void k_matvec(const float* __restrict__ Mat, const float* __restrict__ x,
                         float* __restrict__ y, const float* __restrict__ logd) {
    int gw   = (blockIdx.x*blockDim.x + threadIdx.x) >> 5;
    int lane = threadIdx.x & 31;
    if (gw >= Nh) return;
    const float4* r  = (const float4*)(Mat + (size_t)gw*Nh);
    const float4* xv = (const float4*)x;
    float acc = 0.f;
    #pragma unroll 4
    for (int j = lane; j < Nh/4; j += 32) {
        float4 a = r[j], b = xv[j];
        acc += a.x*b.x + a.y*b.y + a.z*b.z + a.w*b.w;
    }
    #pragma unroll
    for (int o = 16; o; o >>= 1) acc += __shfl_down_sync(0xffffffffu, acc, o);
    if (lane == 0) {
        float s = 1.f;
        if (logd) s = (float)exp((double)logd[0]);
        y[gw] = s*acc;
    }
}

// ---------------- K[t1 + 512*t2] = dot(U[t1,:], W[t2,:]) ----------------
__global__ void k_gk(const float* __restrict__ U, const float* __restrict__ W,
                     float* __restrict__ K) {
    int gw   = (blockIdx.x*blockDim.x + threadIdx.x) >> 5;
    int lane = threadIdx.x & 31;
    if (gw >= LSEQ) return;
    int t1 = gw & (NT1 - 1);
    int t2 = gw >> 9;
    const float4* u = (const float4*)(U + (size_t)t1*Nh);
    const float4* w = (const float4*)(W + (size_t)t2*Nh);
    float acc = 0.f;
    #pragma unroll 4
    for (int j = lane; j < Nh/4; j += 32) {
        float4 a = u[j], b = w[j];
        acc += a.x*b.x + a.y*b.y + a.z*b.z + a.w*b.w;
    }
    #pragma unroll
    for (int o = 16; o; o >>= 1) acc += __shfl_down_sync(0xffffffffu, acc, o);
    if (lane == 0) K[gw] = acc;
}

// ---------------- causal conv: Y[k] = sum_{t<=k} K[t] X[k-t] + D*X[k] ----------------
__global__ __launch_bounds__(128)
void k_conv(const float* __restrict__ X, const float* __restrict__ K,
            const float* __restrict__ D, float* __restrict__ Y) {
    __shared__ float Ks[256];
    __shared__ float Xs[128];
    const int i  = blockIdx.x;
    const int kk = threadIdx.x;
    float acc = 0.f;
    for (int j = 0; j <= i; j++) {
        int base = (i - j) << 7;
        __syncthreads();
        Xs[kk] = X[(j << 7) + kk];
        int i0 = base - 128 + kk;
        Ks[kk]       = (i0 >= 0) ? K[i0] : 0.f;
        Ks[kk + 128] = K[base + kk];
        __syncthreads();
        #pragma unroll 8
        for (int t = 0; t < 128; t++)
            acc += Ks[kk + 128 - t] * Xs[t];
    }
    int k = (i << 7) + kk;
    Y[k] = acc + D[0]*X[k];
}

// ---------------- host ----------------
extern "C" void kernel_launch(void* const* d_in, const int* in_sizes, int n_in,
                              void* d_out, int out_size) {
    int iX=-1, iA=-1, iB=-1, iC=-1, iD=-1, iLd=-1;
    for (int i = 0; i < n_in; i++) {
        int s = in_sizes[i];
        if      (s == Nh*Nh) iA = i;
        else if (s == LSEQ)  iX = i;
        else if (s == Nh)    { if (iB < 0) iB = i; else iC = i; }
        else if (s == 1)     { if (iD < 0) iD = i; else iLd = i; }
    }
    const float* X    = (const float*)d_in[iX];
    const float* A    = (const float*)d_in[iA];
    const float* Bv   = (const float*)d_in[iB];
    const float* Cv   = (const float*)d_in[iC];
    const float* Dv   = (const float*)d_in[iD];
    const float* logd = (const float*)d_in[iLd];
    float* Y = (float*)d_out;
    (void)out_size;

    float *pS, *pT, *pP, *pM, *pU, *pW, *pK;
    cudaGetSymbolAddress((void**)&pS, g_S);
    cudaGetSymbolAddress((void**)&pT, g_T);
    cudaGetSymbolAddress((void**)&pP, g_P);
    cudaGetSymbolAddress((void**)&pM, g_M);
    cudaGetSymbolAddress((void**)&pU, g_U);
    cudaGetSymbolAddress((void**)&pW, g_W);
    cudaGetSymbolAddress((void**)&pK, g_K);

    const int EW = (Nh*Nh)/256;
    dim3 g2(Nh/BN, Nh/BM);   // 16 x 8

    // S = (d/2) A   -> g_S
    k_prep<<<EW, 256>>>(A, logd, pS);
    // P0 = I + S + S^2                      -> g_P
    k_gemm<MODE_P0><<<g2, NTHR>>>(pS, pS, pP, pS, nullptr, Nh);
    // R  = 2I - P0 + S@P0                   -> g_T
    k_gemm<MODE_R ><<<g2, NTHR>>>(pS, pP, pT, pP, nullptr, Nh);
    // P  = P0@R -> g_S ;  M = 2P - I -> g_M
    k_gemm<MODE_PM><<<g2, NTHR>>>(pP, pT, pS, nullptr, pM, Nh);

    k_matvec<<<128, 256>>>(pS, Bv, pW, logd);      // W[0] = dB = d * P @ B
    k_copy<<<4, 256>>>(Cv, pU, Nh);                // U[0] = c

    // Fused doubling: U[rows..2rows) = U @ M^{2^s}, M^{2^{s+1}} = (M^{2^s})^2
    float* pw   = pM;
    float* ping = pP;
    float* pong = pT;
    int rows = 1;
    for (int s = 0; s < 9; s++) {
        int urt = (rows + BM - 1)/BM;
        dim3 gs(Nh/BN, 8 + urt);
        k_step<<<gs, NTHR>>>(pU, pw, pU + (size_t)rows*Nh, rows, ping);
        pw = ping;
        float* tmp = ping; ping = pong; pong = tmp;
        rows <<= 1;
    }
    // pw = M^512

    // W[t] = M^512 @ W[t-1], t = 1..31
    for (int t = 1; t < NT2; t++)
        k_matvec<<<128, 256>>>(pw, pW + (size_t)(t-1)*Nh, pW + (size_t)t*Nh, nullptr);

    // K[t1 + 512*t2] = U[t1] . W[t2]
    k_gk<<<LSEQ/8, 256>>>(pU, pW, pK);

    // y = K (*) X + D*X
    k_conv<<<LSEQ/128, 128>>>(X, pK, Dv, Y);
}

// round 8
// speedup vs baseline: 1.5557x; 1.1389x over previous
#include <cuda_runtime.h>
#include <math.h>
#include <stddef.h>

#define Nh   1024
#define LSEQ 16384
#define NT1  512
#define NT2  32

// ---------------- static device scratch ----------------
__device__ float g_S[Nh*Nh];
__device__ float g_T[Nh*Nh];
__device__ float g_P[Nh*Nh];
__device__ float g_M[Nh*Nh];
__device__ float g_U[NT1*Nh];
__device__ float g_W[NT2*Nh];
__device__ float g_K[LSEQ];

// ---------------- helpers ----------------
__device__ __forceinline__ unsigned smem_u32(const void* p) {
    return (unsigned)__cvta_generic_to_shared(p);
}
__device__ __forceinline__ void cp16(unsigned dst, const void* src) {
    asm volatile("cp.async.cg.shared.global [%0], [%1], 16;\n" :: "r"(dst), "l"(src));
}
__device__ __forceinline__ void ffma2(unsigned long long& acc,
                                      unsigned long long a, unsigned long long b) {
    asm("fma.rn.f32x2 %0, %1, %2, %0;" : "+l"(acc) : "l"(a), "l"(b));
}
__device__ __forceinline__ unsigned long long dupf(float x) {
    unsigned long long r; unsigned u = __float_as_uint(x);
    asm("mov.b64 %0,{%1,%1};" : "=l"(r) : "r"(u));
    return r;
}

// ---------------- elementwise ----------------
__global__ void k_prep(const float* __restrict__ A, const float* __restrict__ logd,
                       float* __restrict__ S) {
    int i = blockIdx.x*blockDim.x + threadIdx.x;
    float d = (float)exp((double)logd[0]);
    S[i] = 0.5f*d*A[i];
}
__global__ void k_copy(const float* __restrict__ src, float* __restrict__ dst, int n) {
    int i = blockIdx.x*blockDim.x + threadIdx.x;
    if (i < n) dst[i] = src[i];
}

// ---------------- GEMM: 128x64 tile, BK=16, 128 thr, 8x8 micro (f32x2) ----
// Conflict-free B fragment: each thread handles cols {tx*4..+3} u {32+tx*4..+3}
// so both LDS.128 B reads are lane-contiguous (1 wavefront per subpass).
#define BM 128
#define BN 64
#define BK 16
#define NTHR 128

#define MODE_PLAIN 0
#define MODE_P0    1   // C = I + E + A@B
#define MODE_R     2   // C = 2I - E + A@B
#define MODE_PM    3   // C = A@B ; C2 = 2*(A@B) - I

template<int MODE>
__device__ __forceinline__ void gemm_tile(const float* __restrict__ A,
                                          const float* __restrict__ B,
                                          float* __restrict__ C,
                                          const float* __restrict__ E,
                                          float* __restrict__ C2,
                                          int Mrows, int bm, int bn) {
    __shared__ __align__(16) float As[2][BK][BM];   // 16 KB, transposed As[b][k][m]
    __shared__ __align__(16) float Bs[2][BK][BN];   // 8 KB
    const int tid = threadIdx.x;
    const int tx = tid & 7;          // n cols: g*32 + tx*4 + j
    const int ty = tid >> 3;         // m0 = ty*8

    unsigned long long acc[4][8];
    #pragma unroll
    for (int p = 0; p < 4; p++)
        #pragma unroll
        for (int j = 0; j < 8; j++) acc[p][j] = 0ULL;

    const bool arow_ok = (bm + tid) < Mrows;
    const float* arow = A + (size_t)(bm + tid)*Nh;
    const unsigned bs_addr[2] = { smem_u32(&Bs[0][0][0]), smem_u32(&Bs[1][0][0]) };
    const int brow = tid >> 4;             // base k-row; second slot at +8
    const int bq4  = (tid & 15) << 2;      // col quad

    float4 areg[4];
    // ---- prologue: tile 0 ----
    #pragma unroll
    for (int q = 0; q < 4; q++)
        areg[q] = arow_ok ? *(const float4*)(arow + q*4) : make_float4(0.f,0.f,0.f,0.f);
    #pragma unroll
    for (int l = 0; l < 2; l++) {
        int r = brow + l*8;
        cp16(bs_addr[0] + (unsigned)(r*BN + bq4)*4, B + (size_t)r*Nh + bn + bq4);
    }
    asm volatile("cp.async.commit_group;\n" ::: "memory");
    #pragma unroll
    for (int q = 0; q < 4; q++) {
        As[0][q*4+0][tid] = areg[q].x; As[0][q*4+1][tid] = areg[q].y;
        As[0][q*4+2][tid] = areg[q].z; As[0][q*4+3][tid] = areg[q].w;
    }
    asm volatile("cp.async.wait_group 0;\n" ::: "memory");
    __syncthreads();

    const int ntiles = Nh / BK;   // 64
    int buf = 0;
    for (int t = 0; t < ntiles; t++) {
        if (t + 1 < ntiles) {
            int kt = (t + 1)*BK;
            #pragma unroll
            for (int q = 0; q < 4; q++)
                areg[q] = arow_ok ? *(const float4*)(arow + kt + q*4)
                                  : make_float4(0.f,0.f,0.f,0.f);
            unsigned bsn = bs_addr[buf ^ 1];
            #pragma unroll
            for (int l = 0; l < 2; l++) {
                int r = brow + l*8;
                cp16(bsn + (unsigned)(r*BN + bq4)*4, B + (size_t)(kt + r)*Nh + bn + bq4);
            }
            asm volatile("cp.async.commit_group;\n" ::: "memory");
        }
        #pragma unroll
        for (int k = 0; k < BK; k++) {
            ulonglong2 a01 = *(const ulonglong2*)(&As[buf][k][ty*8]);
            ulonglong2 a23 = *(const ulonglong2*)(&As[buf][k][ty*8 + 4]);
            float4 b0 = *(const float4*)(&Bs[buf][k][tx*4]);        // lane-contiguous
            float4 b1 = *(const float4*)(&Bs[buf][k][32 + tx*4]);   // lane-contiguous
            unsigned long long a[4] = {a01.x, a01.y, a23.x, a23.y};
            unsigned long long bb[8] = {dupf(b0.x), dupf(b0.y), dupf(b0.z), dupf(b0.w),
                                        dupf(b1.x), dupf(b1.y), dupf(b1.z), dupf(b1.w)};
            #pragma unroll
            for (int p = 0; p < 4; p++)
                #pragma unroll
                for (int j = 0; j < 8; j++)
                    ffma2(acc[p][j], a[p], bb[j]);
        }
        if (t + 1 < ntiles) {
            int nb = buf ^ 1;
            #pragma unroll
            for (int q = 0; q < 4; q++) {
                As[nb][q*4+0][tid] = areg[q].x; As[nb][q*4+1][tid] = areg[q].y;
                As[nb][q*4+2][tid] = areg[q].z; As[nb][q*4+3][tid] = areg[q].w;
            }
            asm volatile("cp.async.wait_group 0;\n" ::: "memory");
        }
        __syncthreads();
        buf ^= 1;
    }

    // ---- epilogue: cols for group g are bn + g*32 + tx*4 ----
    #pragma unroll
    for (int p = 0; p < 4; p++) {
        float lo[8], hi[8];
        #pragma unroll
        for (int j = 0; j < 8; j++) {
            lo[j] = __uint_as_float((unsigned)(acc[p][j]));
            hi[j] = __uint_as_float((unsigned)(acc[p][j] >> 32));
        }
        #pragma unroll
        for (int h = 0; h < 2; h++) {
            int m = bm + ty*8 + 2*p + h;
            float* vr = h ? hi : lo;
            #pragma unroll
            for (int g = 0; g < 2; g++) {
                int nc = bn + g*32 + tx*4;
                float4 v = make_float4(vr[g*4], vr[g*4+1], vr[g*4+2], vr[g*4+3]);
                if (MODE == MODE_P0 || MODE == MODE_R) {
                    float4 e = *(const float4*)(E + (size_t)m*Nh + nc);
                    if (MODE == MODE_P0) {
                        v.x += e.x; v.y += e.y; v.z += e.z; v.w += e.w;
                        if (m == nc)   v.x += 1.f; if (m == nc+1) v.y += 1.f;
                        if (m == nc+2) v.z += 1.f; if (m == nc+3) v.w += 1.f;
                    } else {
                        v.x -= e.x; v.y -= e.y; v.z -= e.z; v.w -= e.w;
                        if (m == nc)   v.x += 2.f; if (m == nc+1) v.y += 2.f;
                        if (m == nc+2) v.z += 2.f; if (m == nc+3) v.w += 2.f;
                    }
                }
                if (MODE == MODE_PLAIN) {
                    if (m < Mrows) *(float4*)(C + (size_t)m*Nh + nc) = v;
                } else {
                    *(float4*)(C + (size_t)m*Nh + nc) = v;
                }
                if (MODE == MODE_PM) {
                    float4 w;
                    w.x = 2.f*v.x; w.y = 2.f*v.y; w.z = 2.f*v.z; w.w = 2.f*v.w;
                    if (m == nc)   w.x -= 1.f; if (m == nc+1) w.y -= 1.f;
                    if (m == nc+2) w.z -= 1.f; if (m == nc+3) w.w -= 1.f;
                    *(float4*)(C2 + (size_t)m*Nh + nc) = w;
                }
            }
        }
    }
}

template<int MODE>
__global__ __launch_bounds__(NTHR)
void k_gemm(const float* __restrict__ A, const float* __restrict__ B,
            float* __restrict__ C, const float* __restrict__ E,
            float* __restrict__ C2, int Mrows) {
    gemm_tile<MODE>(A, B, C, E, C2, Mrows, blockIdx.y*BM, blockIdx.x*BN);
}

// Fused doubling: y<8 -> Psq = Pw@Pw ; y>=8 -> Unext = U[0..rows)@Pw
__global__ __launch_bounds__(NTHR)
void k_step(const float* __restrict__ U, const float* __restrict__ Pw,
            float* __restrict__ Unext, int rows, float* __restrict__ Psq) {
    int by = blockIdx.y;
    if (by < 8)
        gemm_tile<MODE_PLAIN>(Pw, Pw, Psq, nullptr, nullptr, Nh, by*BM, blockIdx.x*BN);
    else
        gemm_tile<MODE_PLAIN>(U, Pw, Unext, nullptr, nullptr, rows, (by - 8)*BM, blockIdx.x*BN);
}

// ---------------- matvec: y = Mat @ x, optional scale exp(logd) ----------------
__global__ void k_matvec(const float* __restrict__ Mat, const float* __restrict__ x,
                         float* __restrict__ y, const float* __restrict__ logd) {
    int gw   = (blockIdx.x*blockDim.x + threadIdx.x) >> 5;
    int lane = threadIdx.x & 31;
    if (gw >= Nh) return;
    const float4* r  = (const float4*)(Mat + (size_t)gw*Nh);
    const float4* xv = (const float4*)x;
    float acc = 0.f;
    #pragma unroll 4
    for (int j = lane; j < Nh/4; j += 32) {
        float4 a = r[j], b = xv[j];
        acc += a.x*b.x + a.y*b.y + a.z*b.z + a.w*b.w;
    }
    #pragma unroll
    for (int o = 16; o; o >>= 1) acc += __shfl_down_sync(0xffffffffu, acc, o);
    if (lane == 0) {
        float s = 1.f;
        if (logd) s = (float)exp((double)logd[0]);
        y[gw] = s*acc;
    }
}

// ---------------- K[t1 + 512*t2] = dot(U[t1,:], W[t2,:]) ----------------
__global__ void k_gk(const float* __restrict__ U, const float* __restrict__ W,
                     float* __restrict__ K) {
    int gw   = (blockIdx.x*blockDim.x + threadIdx.x) >> 5;
    int lane = threadIdx.x & 31;
    if (gw >= LSEQ) return;
    int t1 = gw & (NT1 - 1);
    int t2 = gw >> 9;
    const float4* u = (const float4*)(U + (size_t)t1*Nh);
    const float4* w = (const float4*)(W + (size_t)t2*Nh);
    float acc = 0.f;
    #pragma unroll 4
    for (int j = lane; j < Nh/4; j += 32) {
        float4 a = u[j], b = w[j];
        acc += a.x*b.x + a.y*b.y + a.z*b.z + a.w*b.w;
    }
    #pragma unroll
    for (int o = 16; o; o >>= 1) acc += __shfl_down_sync(0xffffffffu, acc, o);
    if (lane == 0) K[gw] = acc;
}

// ---------------- causal conv: Y[k] = sum_{t<=k} K[t] X[k-t] + D*X[k] ----------------
__global__ __launch_bounds__(128)
void k_conv(const float* __restrict__ X, const float* __restrict__ K,
            const float* __restrict__ D, float* __restrict__ Y) {
    __shared__ float Ks[256];
    __shared__ float Xs[128];
    const int i  = blockIdx.x;
    const int kk = threadIdx.x;
    float acc = 0.f;
    for (int j = 0; j <= i; j++) {
        int base = (i - j) << 7;
        __syncthreads();
        Xs[kk] = X[(j << 7) + kk];
        int i0 = base - 128 + kk;
        Ks[kk]       = (i0 >= 0) ? K[i0] : 0.f;
        Ks[kk + 128] = K[base + kk];
        __syncthreads();
        #pragma unroll 8
        for (int t = 0; t < 128; t++)
            acc += Ks[kk + 128 - t] * Xs[t];
    }
    int k = (i << 7) + kk;
    Y[k] = acc + D[0]*X[k];
}

// ---------------- host ----------------
extern "C" void kernel_launch(void* const* d_in, const int* in_sizes, int n_in,
                              void* d_out, int out_size) {
    int iX=-1, iA=-1, iB=-1, iC=-1, iD=-1, iLd=-1;
    for (int i = 0; i < n_in; i++) {
        int s = in_sizes[i];
        if      (s == Nh*Nh) iA = i;
        else if (s == LSEQ)  iX = i;
        else if (s == Nh)    { if (iB < 0) iB = i; else iC = i; }
        else if (s == 1)     { if (iD < 0) iD = i; else iLd = i; }
    }
    const float* X    = (const float*)d_in[iX];
    const float* A    = (const float*)d_in[iA];
    const float* Bv   = (const float*)d_in[iB];
    const float* Cv   = (const float*)d_in[iC];
    const float* Dv   = (const float*)d_in[iD];
    const float* logd = (const float*)d_in[iLd];
    float* Y = (float*)d_out;
    (void)out_size;

    float *pS, *pT, *pP, *pM, *pU, *pW, *pK;
    cudaGetSymbolAddress((void**)&pS, g_S);
    cudaGetSymbolAddress((void**)&pT, g_T);
    cudaGetSymbolAddress((void**)&pP, g_P);
    cudaGetSymbolAddress((void**)&pM, g_M);
    cudaGetSymbolAddress((void**)&pU, g_U);
    cudaGetSymbolAddress((void**)&pW, g_W);
    cudaGetSymbolAddress((void**)&pK, g_K);

    const int EW = (Nh*Nh)/256;
    dim3 g2(Nh/BN, Nh/BM);   // 16 x 8

    // S = (d/2) A   -> g_S
    k_prep<<<EW, 256>>>(A, logd, pS);
    // P0 = I + S + S^2                      -> g_P
    k_gemm<MODE_P0><<<g2, NTHR>>>(pS, pS, pP, pS, nullptr, Nh);
    // R  = 2I - P0 + S@P0                   -> g_T
    k_gemm<MODE_R ><<<g2, NTHR>>>(pS, pP, pT, pP, nullptr, Nh);
    // P  = P0@R -> g_S ;  M = 2P - I -> g_M
    k_gemm<MODE_PM><<<g2, NTHR>>>(pP, pT, pS, nullptr, pM, Nh);

    k_matvec<<<128, 256>>>(pS, Bv, pW, logd);      // W[0] = dB = d * P @ B
    k_copy<<<4, 256>>>(Cv, pU, Nh);                // U[0] = c

    // Fused doubling: U[rows..2rows) = U @ M^{2^s}, M^{2^{s+1}} = (M^{2^s})^2
    float* pw   = pM;
    float* ping = pP;
    float* pong = pT;
    int rows = 1;
    for (int s = 0; s < 9; s++) {
        int urt = (rows + BM - 1)/BM;
        dim3 gs(Nh/BN, 8 + urt);
        k_step<<<gs, NTHR>>>(pU, pw, pU + (size_t)rows*Nh, rows, ping);
        pw = ping;
        float* tmp = ping; ping = pong; pong = tmp;
        rows <<= 1;
    }
    // pw = M^512

    // W[t] = M^512 @ W[t-1], t = 1..31
    for (int t = 1; t < NT2; t++)
        k_matvec<<<128, 256>>>(pw, pW + (size_t)(t-1)*Nh, pW + (size_t)t*Nh, nullptr);

    // K[t1 + 512*t2] = U[t1] . W[t2]
    k_gk<<<LSEQ/8, 256>>>(pU, pW, pK);

    // y = K (*) X + D*X
    k_conv<<<LSEQ/128, 128>>>(X, pK, Dv, Y);
}

// round 10
// speedup vs baseline: 1.6239x; 1.0438x over previous
#include <cuda_runtime.h>
#include <math.h>
#include <stddef.h>

#define Nh   1024
#define LSEQ 16384
#define NT1  512
#define NT2  32

// ---------------- static device scratch ----------------
__device__ float g_S[Nh*Nh];
__device__ float g_T[Nh*Nh];
__device__ float g_P[Nh*Nh];
__device__ float g_M[Nh*Nh];
__device__ float g_U[NT1*Nh];
__device__ float g_W[NT2*Nh];
__device__ float g_K[LSEQ];

// ---------------- helpers ----------------
__device__ __forceinline__ unsigned smem_u32(const void* p) {
    return (unsigned)__cvta_generic_to_shared(p);
}
__device__ __forceinline__ void cp16(unsigned dst, const void* src) {
    asm volatile("cp.async.cg.shared.global [%0], [%1], 16;\n" :: "r"(dst), "l"(src));
}
__device__ __forceinline__ void ffma2(unsigned long long& acc,
                                      unsigned long long a, unsigned long long b) {
    asm("fma.rn.f32x2 %0, %1, %2, %0;" : "+l"(acc) : "l"(a), "l"(b));
}
__device__ __forceinline__ unsigned long long dupf(float x) {
    unsigned long long r; unsigned u = __float_as_uint(x);
    asm("mov.b64 %0,{%1,%1};" : "=l"(r) : "r"(u));
    return r;
}

// ---------------- elementwise ----------------
__global__ void k_prep(const float* __restrict__ A, const float* __restrict__ logd,
                       float* __restrict__ S) {
    int i = blockIdx.x*blockDim.x + threadIdx.x;
    float d = (float)exp((double)logd[0]);
    S[i] = 0.5f*d*A[i];
}
__global__ void k_copy(const float* __restrict__ src, float* __restrict__ dst, int n) {
    int i = blockIdx.x*blockDim.x + threadIdx.x;
    if (i < n) dst[i] = src[i];
}

// ---------------- GEMM: 64x64 tile, BK=16, 128 thr, 4Mx8N micro (f32x2) ----
// Conflict-free B fragment (cols {tx*4..+3} u {32+tx*4..+3}); grid 256 CTAs.
#define BM 64
#define BN 64
#define BK 16
#define NTHR 128

#define MODE_PLAIN 0
#define MODE_P0    1   // C = I + E + A@B
#define MODE_R     2   // C = 2I - E + A@B
#define MODE_PM    3   // C = A@B ; C2 = 2*(A@B) - I

template<int MODE>
__device__ __forceinline__ void gemm_tile(const float* __restrict__ A,
                                          const float* __restrict__ B,
                                          float* __restrict__ C,
                                          const float* __restrict__ E,
                                          float* __restrict__ C2,
                                          int Mrows, int bm, int bn) {
    __shared__ __align__(16) float As[2][BK][BM];   // 8 KB, transposed As[b][k][m]
    __shared__ __align__(16) float Bs[2][BK][BN];   // 8 KB
    const int tid = threadIdx.x;
    const int tx = tid & 7;          // n cols: g*32 + tx*4 + j
    const int ty = tid >> 3;         // m0 = ty*4  (ty in 0..15)

    unsigned long long acc[2][8];
    #pragma unroll
    for (int p = 0; p < 2; p++)
        #pragma unroll
        for (int j = 0; j < 8; j++) acc[p][j] = 0ULL;

    // global-load mapping (A: 64 rows x 16k; one row, two quads per thread)
    const int ar  = tid >> 1;              // 0..63
    const int af0 = (tid & 1) << 3;        // k-offset 0 or 8
    const bool arow_ok = (bm + ar) < Mrows;
    const float* arow = A + (size_t)(bm + ar)*Nh + af0;
    // B: 16 k-rows x 64 cols; one row, two quads per thread
    const int br  = tid >> 3;              // 0..15
    const int bc0 = (tid & 7) << 3;        // col offset 0..56 step 8
    const unsigned bs_addr[2] = { smem_u32(&Bs[0][0][0]), smem_u32(&Bs[1][0][0]) };

    float4 va0, va1;
    // ---- prologue: tile 0 ----
    va0 = arow_ok ? *(const float4*)(arow)     : make_float4(0.f,0.f,0.f,0.f);
    va1 = arow_ok ? *(const float4*)(arow + 4) : make_float4(0.f,0.f,0.f,0.f);
    cp16(bs_addr[0] + (unsigned)(br*BN + bc0    )*4, B + (size_t)br*Nh + bn + bc0);
    cp16(bs_addr[0] + (unsigned)(br*BN + bc0 + 4)*4, B + (size_t)br*Nh + bn + bc0 + 4);
    asm volatile("cp.async.commit_group;\n" ::: "memory");
    As[0][af0+0][ar] = va0.x; As[0][af0+1][ar] = va0.y;
    As[0][af0+2][ar] = va0.z; As[0][af0+3][ar] = va0.w;
    As[0][af0+4][ar] = va1.x; As[0][af0+5][ar] = va1.y;
    As[0][af0+6][ar] = va1.z; As[0][af0+7][ar] = va1.w;
    asm volatile("cp.async.wait_group 0;\n" ::: "memory");
    __syncthreads();

    const int ntiles = Nh / BK;   // 64
    int buf = 0;
    for (int t = 0; t < ntiles; t++) {
        if (t + 1 < ntiles) {
            int kt = (t + 1)*BK;
            va0 = arow_ok ? *(const float4*)(arow + kt)     : make_float4(0.f,0.f,0.f,0.f);
            va1 = arow_ok ? *(const float4*)(arow + kt + 4) : make_float4(0.f,0.f,0.f,0.f);
            unsigned bsn = bs_addr[buf ^ 1];
            cp16(bsn + (unsigned)(br*BN + bc0    )*4, B + (size_t)(kt + br)*Nh + bn + bc0);
            cp16(bsn + (unsigned)(br*BN + bc0 + 4)*4, B + (size_t)(kt + br)*Nh + bn + bc0 + 4);
            asm volatile("cp.async.commit_group;\n" ::: "memory");
        }
        #pragma unroll
        for (int k = 0; k < BK; k++) {
            ulonglong2 av = *(const ulonglong2*)(&As[buf][k][ty*4]);
            float4 b0 = *(const float4*)(&Bs[buf][k][tx*4]);        // lane-contiguous
            float4 b1 = *(const float4*)(&Bs[buf][k][32 + tx*4]);   // lane-contiguous
            unsigned long long bb[8] = {dupf(b0.x), dupf(b0.y), dupf(b0.z), dupf(b0.w),
                                        dupf(b1.x), dupf(b1.y), dupf(b1.z), dupf(b1.w)};
            #pragma unroll
            for (int j = 0; j < 8; j++) {
                ffma2(acc[0][j], av.x, bb[j]);
                ffma2(acc[1][j], av.y, bb[j]);
            }
        }
        if (t + 1 < ntiles) {
            int nb = buf ^ 1;
            As[nb][af0+0][ar] = va0.x; As[nb][af0+1][ar] = va0.y;
            As[nb][af0+2][ar] = va0.z; As[nb][af0+3][ar] = va0.w;
            As[nb][af0+4][ar] = va1.x; As[nb][af0+5][ar] = va1.y;
            As[nb][af0+6][ar] = va1.z; As[nb][af0+7][ar] = va1.w;
            asm volatile("cp.async.wait_group 0;\n" ::: "memory");
        }
        __syncthreads();
        buf ^= 1;
    }

    // ---- epilogue: cols for group g are bn + g*32 + tx*4 ----
    #pragma unroll
    for (int p = 0; p < 2; p++) {
        float lo[8], hi[8];
        #pragma unroll
        for (int j = 0; j < 8; j++) {
            lo[j] = __uint_as_float((unsigned)(acc[p][j]));
            hi[j] = __uint_as_float((unsigned)(acc[p][j] >> 32));
        }
        #pragma unroll
        for (int h = 0; h < 2; h++) {
            int m = bm + ty*4 + 2*p + h;
            float* vr = h ? hi : lo;
            #pragma unroll
            for (int g = 0; g < 2; g++) {
                int nc = bn + g*32 + tx*4;
                float4 v = make_float4(vr[g*4], vr[g*4+1], vr[g*4+2], vr[g*4+3]);
                if (MODE == MODE_P0 || MODE == MODE_R) {
                    float4 e = *(const float4*)(E + (size_t)m*Nh + nc);
                    if (MODE == MODE_P0) {
                        v.x += e.x; v.y += e.y; v.z += e.z; v.w += e.w;
                        if (m == nc)   v.x += 1.f; if (m == nc+1) v.y += 1.f;
                        if (m == nc+2) v.z += 1.f; if (m == nc+3) v.w += 1.f;
                    } else {
                        v.x -= e.x; v.y -= e.y; v.z -= e.z; v.w -= e.w;
                        if (m == nc)   v.x += 2.f; if (m == nc+1) v.y += 2.f;
                        if (m == nc+2) v.z += 2.f; if (m == nc+3) v.w += 2.f;
                    }
                }
                if (MODE == MODE_PLAIN) {
                    if (m < Mrows) *(float4*)(C + (size_t)m*Nh + nc) = v;
                } else {
                    *(float4*)(C + (size_t)m*Nh + nc) = v;
                }
                if (MODE == MODE_PM) {
                    float4 w;
                    w.x = 2.f*v.x; w.y = 2.f*v.y; w.z = 2.f*v.z; w.w = 2.f*v.w;
                    if (m == nc)   w.x -= 1.f; if (m == nc+1) w.y -= 1.f;
                    if (m == nc+2) w.z -= 1.f; if (m == nc+3) w.w -= 1.f;
                    *(float4*)(C2 + (size_t)m*Nh + nc) = w;
                }
            }
        }
    }
}

template<int MODE>
__global__ __launch_bounds__(NTHR)
void k_gemm(const float* __restrict__ A, const float* __restrict__ B,
            float* __restrict__ C, const float* __restrict__ E,
            float* __restrict__ C2, int Mrows) {
    gemm_tile<MODE>(A, B, C, E, C2, Mrows, blockIdx.y*BM, blockIdx.x*BN);
}

// Fused doubling: y<16 -> Psq = Pw@Pw ; y>=16 -> Unext = U[0..rows)@Pw
__global__ __launch_bounds__(NTHR)
void k_step(const float* __restrict__ U, const float* __restrict__ Pw,
            float* __restrict__ Unext, int rows, float* __restrict__ Psq) {
    int by = blockIdx.y;
    if (by < 16)
        gemm_tile<MODE_PLAIN>(Pw, Pw, Psq, nullptr, nullptr, Nh, by*BM, blockIdx.x*BN);
    else
        gemm_tile<MODE_PLAIN>(U, Pw, Unext, nullptr, nullptr, rows, (by - 16)*BM, blockIdx.x*BN);
}

// ---------------- matvec: y = Mat @ x, optional scale exp(logd) ----------------
__global__ void k_matvec(const float* __restrict__ Mat, const float* __restrict__ x,
                         float* __restrict__ y, const float* __restrict__ logd) {
    int gw   = (blockIdx.x*blockDim.x + threadIdx.x) >> 5;
    int lane = threadIdx.x & 31;
    if (gw >= Nh) return;
    const float4* r  = (const float4*)(Mat + (size_t)gw*Nh);
    const float4* xv = (const float4*)x;
    float acc = 0.f;
    #pragma unroll 4
    for (int j = lane; j < Nh/4; j += 32) {
        float4 a = r[j], b = xv[j];
        acc += a.x*b.x + a.y*b.y + a.z*b.z + a.w*b.w;
    }
    #pragma unroll
    for (int o = 16; o; o >>= 1) acc += __shfl_down_sync(0xffffffffu, acc, o);
    if (lane == 0) {
        float s = 1.f;
        if (logd) s = (float)exp((double)logd[0]);
        y[gw] = s*acc;
    }
}

// ---------------- K[t1 + 512*t2] = dot(U[t1,:], W[t2,:]) ----------------
__global__ void k_gk(const float* __restrict__ U, const float* __restrict__ W,
                     float* __restrict__ K) {
    int gw   = (blockIdx.x*blockDim.x + threadIdx.x) >> 5;
    int lane = threadIdx.x & 31;
    if (gw >= LSEQ) return;
    int t1 = gw & (NT1 - 1);
    int t2 = gw >> 9;
    const float4* u = (const float4*)(U + (size_t)t1*Nh);
    const float4* w = (const float4*)(W + (size_t)t2*Nh);
    float acc = 0.f;
    #pragma unroll 4
    for (int j = lane; j < Nh/4; j += 32) {
        float4 a = u[j], b = w[j];
        acc += a.x*b.x + a.y*b.y + a.z*b.z + a.w*b.w;
    }
    #pragma unroll
    for (int o = 16; o; o >>= 1) acc += __shfl_down_sync(0xffffffffu, acc, o);
    if (lane == 0) K[gw] = acc;
}

// ---------------- causal conv: Y[k] = sum_{t<=k} K[t] X[k-t] + D*X[k] ----------------
__global__ __launch_bounds__(128)
void k_conv(const float* __restrict__ X, const float* __restrict__ K,
            const float* __restrict__ D, float* __restrict__ Y) {
    __shared__ float Ks[256];
    __shared__ float Xs[128];
    const int i  = blockIdx.x;
    const int kk = threadIdx.x;
    float acc = 0.f;
    for (int j = 0; j <= i; j++) {
        int base = (i - j) << 7;
        __syncthreads();
        Xs[kk] = X[(j << 7) + kk];
        int i0 = base - 128 + kk;
        Ks[kk]       = (i0 >= 0) ? K[i0] : 0.f;
        Ks[kk + 128] = K[base + kk];
        __syncthreads();
        #pragma unroll 8
        for (int t = 0; t < 128; t++)
            acc += Ks[kk + 128 - t] * Xs[t];
    }
    int k = (i << 7) + kk;
    Y[k] = acc + D[0]*X[k];
}

// ---------------- host ----------------
extern "C" void kernel_launch(void* const* d_in, const int* in_sizes, int n_in,
                              void* d_out, int out_size) {
    int iX=-1, iA=-1, iB=-1, iC=-1, iD=-1, iLd=-1;
    for (int i = 0; i < n_in; i++) {
        int s = in_sizes[i];
        if      (s == Nh*Nh) iA = i;
        else if (s == LSEQ)  iX = i;
        else if (s == Nh)    { if (iB < 0) iB = i; else iC = i; }
        else if (s == 1)     { if (iD < 0) iD = i; else iLd = i; }
    }
    const float* X    = (const float*)d_in[iX];
    const float* A    = (const float*)d_in[iA];
    const float* Bv   = (const float*)d_in[iB];
    const float* Cv   = (const float*)d_in[iC];
    const float* Dv   = (const float*)d_in[iD];
    const float* logd = (const float*)d_in[iLd];
    float* Y = (float*)d_out;
    (void)out_size;

    float *pS, *pT, *pP, *pM, *pU, *pW, *pK;
    cudaGetSymbolAddress((void**)&pS, g_S);
    cudaGetSymbolAddress((void**)&pT, g_T);
    cudaGetSymbolAddress((void**)&pP, g_P);
    cudaGetSymbolAddress((void**)&pM, g_M);
    cudaGetSymbolAddress((void**)&pU, g_U);
    cudaGetSymbolAddress((void**)&pW, g_W);
    cudaGetSymbolAddress((void**)&pK, g_K);

    const int EW = (Nh*Nh)/256;
    dim3 g2(Nh/BN, Nh/BM);   // 16 x 16 = 256 CTAs

    // S = (d/2) A   -> g_S
    k_prep<<<EW, 256>>>(A, logd, pS);
    // P0 = I + S + S^2                      -> g_P
    k_gemm<MODE_P0><<<g2, NTHR>>>(pS, pS, pP, pS, nullptr, Nh);
    // R  = 2I - P0 + S@P0                   -> g_T
    k_gemm<MODE_R ><<<g2, NTHR>>>(pS, pP, pT, pP, nullptr, Nh);
    // P  = P0@R -> g_S ;  M = 2P - I -> g_M
    k_gemm<MODE_PM><<<g2, NTHR>>>(pP, pT, pS, nullptr, pM, Nh);

    k_matvec<<<128, 256>>>(pS, Bv, pW, logd);      // W[0] = dB = d * P @ B
    k_copy<<<4, 256>>>(Cv, pU, Nh);                // U[0] = c

    // Fused doubling: U[rows..2rows) = U @ M^{2^s}, M^{2^{s+1}} = (M^{2^s})^2
    float* pw   = pM;
    float* ping = pP;
    float* pong = pT;
    int rows = 1;
    for (int s = 0; s < 9; s++) {
        int urt = (rows + BM - 1)/BM;
        dim3 gs(Nh/BN, 16 + urt);
        k_step<<<gs, NTHR>>>(pU, pw, pU + (size_t)rows*Nh, rows, ping);
        pw = ping;
        float* tmp = ping; ping = pong; pong = tmp;
        rows <<= 1;
    }
    // pw = M^512

    // W[t] = M^512 @ W[t-1], t = 1..31
    for (int t = 1; t < NT2; t++)
        k_matvec<<<128, 256>>>(pw, pW + (size_t)(t-1)*Nh, pW + (size_t)t*Nh, nullptr);

    // K[t1 + 512*t2] = U[t1] . W[t2]
    k_gk<<<LSEQ/8, 256>>>(pU, pW, pK);

    // y = K (*) X + D*X
    k_conv<<<LSEQ/128, 128>>>(X, pK, Dv, Y);
}

// round 11
// speedup vs baseline: 1.6566x; 1.0202x over previous
#include <cuda_runtime.h>
#include <math.h>
#include <stddef.h>

#define Nh   1024
#define LSEQ 16384
#define NT1  512
#define NT2  32
#define KS   4
#define KCH  256          // Nh / KS

// ---------------- static device scratch ----------------
__device__ float g_S[Nh*Nh];
__device__ float g_T[Nh*Nh];
__device__ float g_P[Nh*Nh];
__device__ float g_M[Nh*Nh];
__device__ float g_U[NT1*Nh];
__device__ float g_W[NT2*Nh];
__device__ float g_K[LSEQ];
__device__ float g_Q [KS*Nh*Nh];     // split-K partials (full GEMMs)   16 MB
__device__ float g_QU[KS*256*Nh];    // split-K partials (U-extension)   4 MB

// ---------------- helpers ----------------
__device__ __forceinline__ unsigned smem_u32(const void* p) {
    return (unsigned)__cvta_generic_to_shared(p);
}
__device__ __forceinline__ void cp16(unsigned dst, const void* src) {
    asm volatile("cp.async.cg.shared.global [%0], [%1], 16;\n" :: "r"(dst), "l"(src));
}
__device__ __forceinline__ void ffma2(unsigned long long& acc,
                                      unsigned long long a, unsigned long long b) {
    asm("fma.rn.f32x2 %0, %1, %2, %0;" : "+l"(acc) : "l"(a), "l"(b));
}
__device__ __forceinline__ unsigned long long dupf(float x) {
    unsigned long long r; unsigned u = __float_as_uint(x);
    asm("mov.b64 %0,{%1,%1};" : "=l"(r) : "r"(u));
    return r;
}

// ---------------- elementwise ----------------
__global__ void k_prep(const float* __restrict__ A, const float* __restrict__ logd,
                       float* __restrict__ S) {
    int i = blockIdx.x*blockDim.x + threadIdx.x;
    float d = (float)exp((double)logd[0]);
    S[i] = 0.5f*d*A[i];
}
__global__ void k_copy(const float* __restrict__ src, float* __restrict__ dst, int n) {
    int i = blockIdx.x*blockDim.x + threadIdx.x;
    if (i < n) dst[i] = src[i];
}

// ---------------- partial GEMM: 128x64 tile, BK=16, 128 thr, 8x8 micro (f32x2) ----
// R7 inner loop (conflict-free B fragment), K-chunk [k0, k0+256).
#define BM 128
#define BN 64
#define BK 16
#define NTHR 128

__device__ __forceinline__ void gemm_partial(const float* __restrict__ A,
                                             const float* __restrict__ B,
                                             float* __restrict__ Cp,
                                             int Mrows, int bm, int bn, int k0) {
    __shared__ __align__(16) float As[2][BK][BM];
    __shared__ __align__(16) float Bs[2][BK][BN];
    const int tid = threadIdx.x;
    const int tx = tid & 7;          // n cols: g*32 + tx*4 + j
    const int ty = tid >> 3;         // m0 = ty*8

    unsigned long long acc[4][8];
    #pragma unroll
    for (int p = 0; p < 4; p++)
        #pragma unroll
        for (int j = 0; j < 8; j++) acc[p][j] = 0ULL;

    const bool arow_ok = (bm + tid) < Mrows;
    const float* arow = A + (size_t)(bm + tid)*Nh;
    const unsigned bs_addr[2] = { smem_u32(&Bs[0][0][0]), smem_u32(&Bs[1][0][0]) };
    const int brow = tid >> 4;             // base k-row; second slot at +8
    const int bq4  = (tid & 15) << 2;      // col quad

    float4 areg[4];
    // ---- prologue: tile 0 ----
    #pragma unroll
    for (int q = 0; q < 4; q++)
        areg[q] = arow_ok ? *(const float4*)(arow + k0 + q*4) : make_float4(0.f,0.f,0.f,0.f);
    #pragma unroll
    for (int l = 0; l < 2; l++) {
        int r = brow + l*8;
        cp16(bs_addr[0] + (unsigned)(r*BN + bq4)*4, B + (size_t)(k0 + r)*Nh + bn + bq4);
    }
    asm volatile("cp.async.commit_group;\n" ::: "memory");
    #pragma unroll
    for (int q = 0; q < 4; q++) {
        As[0][q*4+0][tid] = areg[q].x; As[0][q*4+1][tid] = areg[q].y;
        As[0][q*4+2][tid] = areg[q].z; As[0][q*4+3][tid] = areg[q].w;
    }
    asm volatile("cp.async.wait_group 0;\n" ::: "memory");
    __syncthreads();

    const int ntiles = KCH / BK;   // 16
    int buf = 0;
    for (int t = 0; t < ntiles; t++) {
        if (t + 1 < ntiles) {
            int kt = k0 + (t + 1)*BK;
            #pragma unroll
            for (int q = 0; q < 4; q++)
                areg[q] = arow_ok ? *(const float4*)(arow + kt + q*4)
                                  : make_float4(0.f,0.f,0.f,0.f);
            unsigned bsn = bs_addr[buf ^ 1];
            #pragma unroll
            for (int l = 0; l < 2; l++) {
                int r = brow + l*8;
                cp16(bsn + (unsigned)(r*BN + bq4)*4, B + (size_t)(kt + r)*Nh + bn + bq4);
            }
            asm volatile("cp.async.commit_group;\n" ::: "memory");
        }
        #pragma unroll
        for (int k = 0; k < BK; k++) {
            ulonglong2 a01 = *(const ulonglong2*)(&As[buf][k][ty*8]);
            ulonglong2 a23 = *(const ulonglong2*)(&As[buf][k][ty*8 + 4]);
            float4 b0 = *(const float4*)(&Bs[buf][k][tx*4]);        // lane-contiguous
            float4 b1 = *(const float4*)(&Bs[buf][k][32 + tx*4]);   // lane-contiguous
            unsigned long long a[4] = {a01.x, a01.y, a23.x, a23.y};
            unsigned long long bb[8] = {dupf(b0.x), dupf(b0.y), dupf(b0.z), dupf(b0.w),
                                        dupf(b1.x), dupf(b1.y), dupf(b1.z), dupf(b1.w)};
            #pragma unroll
            for (int p = 0; p < 4; p++)
                #pragma unroll
                for (int j = 0; j < 8; j++)
                    ffma2(acc[p][j], a[p], bb[j]);
        }
        if (t + 1 < ntiles) {
            int nb = buf ^ 1;
            #pragma unroll
            for (int q = 0; q < 4; q++) {
                As[nb][q*4+0][tid] = areg[q].x; As[nb][q*4+1][tid] = areg[q].y;
                As[nb][q*4+2][tid] = areg[q].z; As[nb][q*4+3][tid] = areg[q].w;
            }
            asm volatile("cp.async.wait_group 0;\n" ::: "memory");
        }
        __syncthreads();
        buf ^= 1;
    }

    // ---- write partial tile ----
    #pragma unroll
    for (int p = 0; p < 4; p++) {
        float lo[8], hi[8];
        #pragma unroll
        for (int j = 0; j < 8; j++) {
            lo[j] = __uint_as_float((unsigned)(acc[p][j]));
            hi[j] = __uint_as_float((unsigned)(acc[p][j] >> 32));
        }
        #pragma unroll
        for (int h = 0; h < 2; h++) {
            int m = bm + ty*8 + 2*p + h;
            if (m >= Mrows) continue;
            float* vr = h ? hi : lo;
            #pragma unroll
            for (int g = 0; g < 2; g++) {
                int nc = bn + g*32 + tx*4;
                *(float4*)(Cp + (size_t)m*Nh + nc) =
                    make_float4(vr[g*4], vr[g*4+1], vr[g*4+2], vr[g*4+3]);
            }
        }
    }
}

__global__ __launch_bounds__(NTHR)
void k_gemm_part(const float* __restrict__ A, const float* __restrict__ B,
                 float* __restrict__ Q, int Mrows) {
    gemm_partial(A, B, Q + (size_t)blockIdx.z*Nh*Nh, Mrows,
                 blockIdx.y*BM, blockIdx.x*BN, blockIdx.z*KCH);
}

// Fused doubling partials: y<8 -> squaring into Qs ; y>=8 -> U-ext into QU
__global__ __launch_bounds__(NTHR)
void k_step_part(const float* __restrict__ U, const float* __restrict__ Pw,
                 int rows, float* __restrict__ Qs, float* __restrict__ QU) {
    int by = blockIdx.y, z = blockIdx.z;
    if (by < 8)
        gemm_partial(Pw, Pw, Qs + (size_t)z*Nh*Nh, Nh, by*BM, blockIdx.x*BN, z*KCH);
    else
        gemm_partial(U, Pw, QU + (size_t)z*(256*Nh), rows, (by - 8)*BM, blockIdx.x*BN, z*KCH);
}

// ---------------- combine kernels ----------------
#define MODE_P0 1   // C = I + E + sum
#define MODE_R  2   // C = 2I - E + sum
#define MODE_PM 3   // C = sum ; C2 = 2*sum - I

__device__ __forceinline__ float4 sum4(const float4* Q, size_t q, size_t SZ) {
    float4 a = Q[q], b = Q[q+SZ], c = Q[q+2*SZ], d = Q[q+3*SZ];
    float4 v;
    v.x = (a.x + b.x) + (c.x + d.x);
    v.y = (a.y + b.y) + (c.y + d.y);
    v.z = (a.z + b.z) + (c.z + d.z);
    v.w = (a.w + b.w) + (c.w + d.w);
    return v;
}

template<int MODE>
__global__ void k_comb(const float* __restrict__ Q, const float* __restrict__ E,
                       float* __restrict__ C, float* __restrict__ C2) {
    int q = blockIdx.x*blockDim.x + threadIdx.x;     // quad id (262144 total)
    const size_t SZ = (size_t)Nh*Nh/4;
    float4 v = sum4((const float4*)Q, (size_t)q, SZ);
    int m  = q >> 8;
    int nc = (q & 255) << 2;
    if (MODE == MODE_P0) {
        float4 e = ((const float4*)E)[q];
        v.x += e.x; v.y += e.y; v.z += e.z; v.w += e.w;
        if (m == nc)   v.x += 1.f; if (m == nc+1) v.y += 1.f;
        if (m == nc+2) v.z += 1.f; if (m == nc+3) v.w += 1.f;
    }
    if (MODE == MODE_R) {
        float4 e = ((const float4*)E)[q];
        v.x -= e.x; v.y -= e.y; v.z -= e.z; v.w -= e.w;
        if (m == nc)   v.x += 2.f; if (m == nc+1) v.y += 2.f;
        if (m == nc+2) v.z += 2.f; if (m == nc+3) v.w += 2.f;
    }
    ((float4*)C)[q] = v;
    if (MODE == MODE_PM) {
        float4 w;
        w.x = 2.f*v.x; w.y = 2.f*v.y; w.z = 2.f*v.z; w.w = 2.f*v.w;
        if (m == nc)   w.x -= 1.f; if (m == nc+1) w.y -= 1.f;
        if (m == nc+2) w.z -= 1.f; if (m == nc+3) w.w -= 1.f;
        ((float4*)C2)[q] = w;
    }
}

__global__ void k_stepcomb(const float* __restrict__ Qs, const float* __restrict__ QU,
                           float* __restrict__ Psq, float* __restrict__ Unext, int rows) {
    int q = blockIdx.x*blockDim.x + threadIdx.x;
    const size_t SZ = (size_t)Nh*Nh/4;
    if (q < (int)SZ) {
        ((float4*)Psq)[q] = sum4((const float4*)Qs, (size_t)q, SZ);
    } else {
        int qq = q - (int)SZ;
        if ((qq >> 8) < rows) {
            const size_t SU = (size_t)256*Nh/4;
            ((float4*)Unext)[qq] = sum4((const float4*)QU, (size_t)qq, SU);
        }
    }
}

// ---------------- matvec: y = Mat @ x, optional scale exp(logd) ----------------
__global__ void k_matvec(const float* __restrict__ Mat, const float* __restrict__ x,
                         float* __restrict__ y, const float* __restrict__ logd) {
    int gw   = (blockIdx.x*blockDim.x + threadIdx.x) >> 5;
    int lane = threadIdx.x & 31;
    if (gw >= Nh) return;
    const float4* r  = (const float4*)(Mat + (size_t)gw*Nh);
    const float4* xv = (const float4*)x;
    float acc = 0.f;
    #pragma unroll 4
    for (int j = lane; j < Nh/4; j += 32) {
        float4 a = r[j], b = xv[j];
        acc += a.x*b.x + a.y*b.y + a.z*b.z + a.w*b.w;
    }
    #pragma unroll
    for (int o = 16; o; o >>= 1) acc += __shfl_down_sync(0xffffffffu, acc, o);
    if (lane == 0) {
        float s = 1.f;
        if (logd) s = (float)exp((double)logd[0]);
        y[gw] = s*acc;
    }
}

// ---------------- K[t1 + 512*t2] = dot(U[t1,:], W[t2,:]) ----------------
__global__ void k_gk(const float* __restrict__ U, const float* __restrict__ W,
                     float* __restrict__ K) {
    int gw   = (blockIdx.x*blockDim.x + threadIdx.x) >> 5;
    int lane = threadIdx.x & 31;
    if (gw >= LSEQ) return;
    int t1 = gw & (NT1 - 1);
    int t2 = gw >> 9;
    const float4* u = (const float4*)(U + (size_t)t1*Nh);
    const float4* w = (const float4*)(W + (size_t)t2*Nh);
    float acc = 0.f;
    #pragma unroll 4
    for (int j = lane; j < Nh/4; j += 32) {
        float4 a = u[j], b = w[j];
        acc += a.x*b.x + a.y*b.y + a.z*b.z + a.w*b.w;
    }
    #pragma unroll
    for (int o = 16; o; o >>= 1) acc += __shfl_down_sync(0xffffffffu, acc, o);
    if (lane == 0) K[gw] = acc;
}

// ---------------- causal conv: Y[k] = sum_{t<=k} K[t] X[k-t] + D*X[k] ----------------
__global__ __launch_bounds__(128)
void k_conv(const float* __restrict__ X, const float* __restrict__ K,
            const float* __restrict__ D, float* __restrict__ Y) {
    __shared__ float Ks[256];
    __shared__ float Xs[128];
    const int i  = blockIdx.x;
    const int kk = threadIdx.x;
    float acc = 0.f;
    for (int j = 0; j <= i; j++) {
        int base = (i - j) << 7;
        __syncthreads();
        Xs[kk] = X[(j << 7) + kk];
        int i0 = base - 128 + kk;
        Ks[kk]       = (i0 >= 0) ? K[i0] : 0.f;
        Ks[kk + 128] = K[base + kk];
        __syncthreads();
        #pragma unroll 8
        for (int t = 0; t < 128; t++)
            acc += Ks[kk + 128 - t] * Xs[t];
    }
    int k = (i << 7) + kk;
    Y[k] = acc + D[0]*X[k];
}

// ---------------- host ----------------
extern "C" void kernel_launch(void* const* d_in, const int* in_sizes, int n_in,
                              void* d_out, int out_size) {
    int iX=-1, iA=-1, iB=-1, iC=-1, iD=-1, iLd=-1;
    for (int i = 0; i < n_in; i++) {
        int s = in_sizes[i];
        if      (s == Nh*Nh) iA = i;
        else if (s == LSEQ)  iX = i;
        else if (s == Nh)    { if (iB < 0) iB = i; else iC = i; }
        else if (s == 1)     { if (iD < 0) iD = i; else iLd = i; }
    }
    const float* X    = (const float*)d_in[iX];
    const float* A    = (const float*)d_in[iA];
    const float* Bv   = (const float*)d_in[iB];
    const float* Cv   = (const float*)d_in[iC];
    const float* Dv   = (const float*)d_in[iD];
    const float* logd = (const float*)d_in[iLd];
    float* Y = (float*)d_out;
    (void)out_size;

    float *pS, *pT, *pP, *pM, *pU, *pW, *pK, *pQ, *pQU;
    cudaGetSymbolAddress((void**)&pS, g_S);
    cudaGetSymbolAddress((void**)&pT, g_T);
    cudaGetSymbolAddress((void**)&pP, g_P);
    cudaGetSymbolAddress((void**)&pM, g_M);
    cudaGetSymbolAddress((void**)&pU, g_U);
    cudaGetSymbolAddress((void**)&pW, g_W);
    cudaGetSymbolAddress((void**)&pK, g_K);
    cudaGetSymbolAddress((void**)&pQ, g_Q);
    cudaGetSymbolAddress((void**)&pQU, g_QU);

    const int EW = (Nh*Nh)/256;
    dim3 gp(Nh/BN, Nh/BM, KS);   // 16 x 8 x 4 = 512 CTAs
    const int CB = (Nh*Nh/4)/256;  // 1024 combine blocks

    // S = (d/2) A   -> g_S
    k_prep<<<EW, 256>>>(A, logd, pS);
    // P0 = I + S + S^2                      -> g_P
    k_gemm_part<<<gp, NTHR>>>(pS, pS, pQ, Nh);
    k_comb<MODE_P0><<<CB, 256>>>(pQ, pS, pP, nullptr);
    // R  = 2I - P0 + S@P0                   -> g_T
    k_gemm_part<<<gp, NTHR>>>(pS, pP, pQ, Nh);
    k_comb<MODE_R ><<<CB, 256>>>(pQ, pP, pT, nullptr);
    // P  = P0@R -> g_S ;  M = 2P - I -> g_M
    k_gemm_part<<<gp, NTHR>>>(pP, pT, pQ, Nh);
    k_comb<MODE_PM><<<CB, 256>>>(pQ, nullptr, pS, pM);

    k_matvec<<<128, 256>>>(pS, Bv, pW, logd);      // W[0] = dB = d * P @ B
    k_copy<<<4, 256>>>(Cv, pU, Nh);                // U[0] = c

    // Fused doubling: U[rows..2rows) = U @ M^{2^s}, M^{2^{s+1}} = (M^{2^s})^2
    float* pw   = pM;
    float* ping = pP;
    float* pong = pT;
    int rows = 1;
    for (int s = 0; s < 9; s++) {
        int urt = (rows + BM - 1)/BM;          // 1 (rows<=128) or 2 (rows=256)
        dim3 gs(Nh/BN, 8 + urt, KS);
        k_step_part<<<gs, NTHR>>>(pU, pw, rows, pQ, pQU);
        int totq = Nh*Nh/4 + rows*(Nh/4);
        k_stepcomb<<<(totq + 255)/256, 256>>>(pQ, pQU, ping, pU + (size_t)rows*Nh, rows);
        pw = ping;
        float* tmp = ping; ping = pong; pong = tmp;
        rows <<= 1;
    }
    // pw = M^512

    // W[t] = M^512 @ W[t-1], t = 1..31
    for (int t = 1; t < NT2; t++)
        k_matvec<<<128, 256>>>(pw, pW + (size_t)(t-1)*Nh, pW + (size_t)t*Nh, nullptr);

    // K[t1 + 512*t2] = U[t1] . W[t2]
    k_gk<<<LSEQ/8, 256>>>(pU, pW, pK);

    // y = K (*) X + D*X
    k_conv<<<LSEQ/128, 128>>>(X, pK, Dv, Y);
}

// round 12
// speedup vs baseline: 1.6577x; 1.0006x over previous
#include <cuda_runtime.h>
#include <math.h>
#include <stddef.h>

#define Nh   1024
#define LSEQ 16384
#define NT1  512
#define NT2  32
#define KS   4
#define KCH  256          // Nh / KS

// ---------------- static device scratch ----------------
__device__ float g_S[Nh*Nh];
__device__ float g_T[Nh*Nh];
__device__ float g_P[Nh*Nh];
__device__ float g_M[Nh*Nh];
__device__ float g_U[NT1*Nh];
__device__ float g_W[NT2*Nh];
__device__ float g_K[LSEQ];
__device__ float g_Q [KS*Nh*Nh];     // split-K partials (full GEMMs)   16 MB
__device__ float g_QU[KS*256*Nh];    // split-K partials (U-extension)   4 MB

// ---------------- helpers ----------------
__device__ __forceinline__ unsigned smem_u32(const void* p) {
    return (unsigned)__cvta_generic_to_shared(p);
}
__device__ __forceinline__ void cp16(unsigned dst, const void* src) {
    asm volatile("cp.async.cg.shared.global [%0], [%1], 16;\n" :: "r"(dst), "l"(src));
}
__device__ __forceinline__ void ffma2(unsigned long long& acc,
                                      unsigned long long a, unsigned long long b) {
    asm("fma.rn.f32x2 %0, %1, %2, %0;" : "+l"(acc) : "l"(a), "l"(b));
}
__device__ __forceinline__ unsigned long long dupf(float x) {
    unsigned long long r; unsigned u = __float_as_uint(x);
    asm("mov.b64 %0,{%1,%1};" : "=l"(r) : "r"(u));
    return r;
}

// ---------------- elementwise ----------------
__global__ void k_prep(const float* __restrict__ A, const float* __restrict__ logd,
                       float* __restrict__ S) {
    int i = blockIdx.x*blockDim.x + threadIdx.x;
    float d = (float)exp((double)logd[0]);
    S[i] = 0.5f*d*A[i];
}
__global__ void k_copy(const float* __restrict__ src, float* __restrict__ dst, int n) {
    int i = blockIdx.x*blockDim.x + threadIdx.x;
    if (i < n) dst[i] = src[i];
}

// ---------------- partial GEMM: 128x64 tile, BK=16, 256 thr, 4Mx8N micro (f32x2) ----
// Conflict-free B fragment; K-chunk [k0, k0+256); high-occupancy variant.
#define BM 128
#define BN 64
#define BK 16
#define NTHR 256

__device__ __forceinline__ void gemm_partial(const float* __restrict__ A,
                                             const float* __restrict__ B,
                                             float* __restrict__ Cp,
                                             int Mrows, int bm, int bn, int k0) {
    __shared__ __align__(16) float As[2][BK][BM];   // 16 KB, transposed As[b][k][m]
    __shared__ __align__(16) float Bs[2][BK][BN];   // 8 KB
    const int tid = threadIdx.x;
    const int tx = tid & 7;          // n cols: g*32 + tx*4 + j
    const int ty = tid >> 3;         // m0 = ty*4  (ty in 0..31)

    unsigned long long acc[2][8];
    #pragma unroll
    for (int p = 0; p < 2; p++)
        #pragma unroll
        for (int j = 0; j < 8; j++) acc[p][j] = 0ULL;

    // A staging: 128 rows x 16 k = 512 float4; 2 per thread
    const int ar  = tid >> 1;              // 0..127
    const int af0 = (tid & 1) << 3;        // k-offset 0 or 8
    const bool arow_ok = (bm + ar) < Mrows;
    const float* arow = A + (size_t)(bm + ar)*Nh + af0;
    // B: 16 k-rows x 64 cols = 256 float4; 1 cp.async per thread
    const int brow = tid >> 4;             // 0..15
    const int bq4  = (tid & 15) << 2;      // col quad
    const unsigned bs_addr[2] = { smem_u32(&Bs[0][0][0]), smem_u32(&Bs[1][0][0]) };

    float4 va0, va1;
    // ---- prologue: tile 0 ----
    va0 = arow_ok ? *(const float4*)(arow + k0)     : make_float4(0.f,0.f,0.f,0.f);
    va1 = arow_ok ? *(const float4*)(arow + k0 + 4) : make_float4(0.f,0.f,0.f,0.f);
    cp16(bs_addr[0] + (unsigned)(brow*BN + bq4)*4, B + (size_t)(k0 + brow)*Nh + bn + bq4);
    asm volatile("cp.async.commit_group;\n" ::: "memory");
    As[0][af0+0][ar] = va0.x; As[0][af0+1][ar] = va0.y;
    As[0][af0+2][ar] = va0.z; As[0][af0+3][ar] = va0.w;
    As[0][af0+4][ar] = va1.x; As[0][af0+5][ar] = va1.y;
    As[0][af0+6][ar] = va1.z; As[0][af0+7][ar] = va1.w;
    asm volatile("cp.async.wait_group 0;\n" ::: "memory");
    __syncthreads();

    const int ntiles = KCH / BK;   // 16
    int buf = 0;
    for (int t = 0; t < ntiles; t++) {
        if (t + 1 < ntiles) {
            int kt = k0 + (t + 1)*BK;
            va0 = arow_ok ? *(const float4*)(arow + kt)     : make_float4(0.f,0.f,0.f,0.f);
            va1 = arow_ok ? *(const float4*)(arow + kt + 4) : make_float4(0.f,0.f,0.f,0.f);
            unsigned bsn = bs_addr[buf ^ 1];
            cp16(bsn + (unsigned)(brow*BN + bq4)*4, B + (size_t)(kt + brow)*Nh + bn + bq4);
            asm volatile("cp.async.commit_group;\n" ::: "memory");
        }
        #pragma unroll
        for (int k = 0; k < BK; k++) {
            ulonglong2 av = *(const ulonglong2*)(&As[buf][k][ty*4]);
            float4 b0 = *(const float4*)(&Bs[buf][k][tx*4]);        // lane-contiguous
            float4 b1 = *(const float4*)(&Bs[buf][k][32 + tx*4]);   // lane-contiguous
            unsigned long long bb[8] = {dupf(b0.x), dupf(b0.y), dupf(b0.z), dupf(b0.w),
                                        dupf(b1.x), dupf(b1.y), dupf(b1.z), dupf(b1.w)};
            #pragma unroll
            for (int j = 0; j < 8; j++) {
                ffma2(acc[0][j], av.x, bb[j]);
                ffma2(acc[1][j], av.y, bb[j]);
            }
        }
        if (t + 1 < ntiles) {
            int nb = buf ^ 1;
            As[nb][af0+0][ar] = va0.x; As[nb][af0+1][ar] = va0.y;
            As[nb][af0+2][ar] = va0.z; As[nb][af0+3][ar] = va0.w;
            As[nb][af0+4][ar] = va1.x; As[nb][af0+5][ar] = va1.y;
            As[nb][af0+6][ar] = va1.z; As[nb][af0+7][ar] = va1.w;
            asm volatile("cp.async.wait_group 0;\n" ::: "memory");
        }
        __syncthreads();
        buf ^= 1;
    }

    // ---- write partial tile ----
    #pragma unroll
    for (int p = 0; p < 2; p++) {
        float lo[8], hi[8];
        #pragma unroll
        for (int j = 0; j < 8; j++) {
            lo[j] = __uint_as_float((unsigned)(acc[p][j]));
            hi[j] = __uint_as_float((unsigned)(acc[p][j] >> 32));
        }
        #pragma unroll
        for (int h = 0; h < 2; h++) {
            int m = bm + ty*4 + 2*p + h;
            if (m >= Mrows) continue;
            float* vr = h ? hi : lo;
            #pragma unroll
            for (int g = 0; g < 2; g++) {
                int nc = bn + g*32 + tx*4;
                *(float4*)(Cp + (size_t)m*Nh + nc) =
                    make_float4(vr[g*4], vr[g*4+1], vr[g*4+2], vr[g*4+3]);
            }
        }
    }
}

__global__ __launch_bounds__(NTHR, 2)
void k_gemm_part(const float* __restrict__ A, const float* __restrict__ B,
                 float* __restrict__ Q, int Mrows) {
    gemm_partial(A, B, Q + (size_t)blockIdx.z*Nh*Nh, Mrows,
                 blockIdx.y*BM, blockIdx.x*BN, blockIdx.z*KCH);
}

// Fused doubling partials: y<8 -> squaring into Qs ; y>=8 -> U-ext into QU
__global__ __launch_bounds__(NTHR, 2)
void k_step_part(const float* __restrict__ U, const float* __restrict__ Pw,
                 int rows, float* __restrict__ Qs, float* __restrict__ QU) {
    int by = blockIdx.y, z = blockIdx.z;
    if (by < 8)
        gemm_partial(Pw, Pw, Qs + (size_t)z*Nh*Nh, Nh, by*BM, blockIdx.x*BN, z*KCH);
    else
        gemm_partial(U, Pw, QU + (size_t)z*(256*Nh), rows, (by - 8)*BM, blockIdx.x*BN, z*KCH);
}

// ---------------- combine kernels ----------------
#define MODE_P0 1   // C = I + E + sum
#define MODE_R  2   // C = 2I - E + sum
#define MODE_PM 3   // C = sum ; C2 = 2*sum - I

__device__ __forceinline__ float4 sum4(const float4* Q, size_t q, size_t SZ) {
    float4 a = Q[q], b = Q[q+SZ], c = Q[q+2*SZ], d = Q[q+3*SZ];
    float4 v;
    v.x = (a.x + b.x) + (c.x + d.x);
    v.y = (a.y + b.y) + (c.y + d.y);
    v.z = (a.z + b.z) + (c.z + d.z);
    v.w = (a.w + b.w) + (c.w + d.w);
    return v;
}

template<int MODE>
__global__ void k_comb(const float* __restrict__ Q, const float* __restrict__ E,
                       float* __restrict__ C, float* __restrict__ C2) {
    int q = blockIdx.x*blockDim.x + threadIdx.x;     // quad id (262144 total)
    const size_t SZ = (size_t)Nh*Nh/4;
    float4 v = sum4((const float4*)Q, (size_t)q, SZ);
    int m  = q >> 8;
    int nc = (q & 255) << 2;
    if (MODE == MODE_P0) {
        float4 e = ((const float4*)E)[q];
        v.x += e.x; v.y += e.y; v.z += e.z; v.w += e.w;
        if (m == nc)   v.x += 1.f; if (m == nc+1) v.y += 1.f;
        if (m == nc+2) v.z += 1.f; if (m == nc+3) v.w += 1.f;
    }
    if (MODE == MODE_R) {
        float4 e = ((const float4*)E)[q];
        v.x -= e.x; v.y -= e.y; v.z -= e.z; v.w -= e.w;
        if (m == nc)   v.x += 2.f; if (m == nc+1) v.y += 2.f;
        if (m == nc+2) v.z += 2.f; if (m == nc+3) v.w += 2.f;
    }
    ((float4*)C)[q] = v;
    if (MODE == MODE_PM) {
        float4 w;
        w.x = 2.f*v.x; w.y = 2.f*v.y; w.z = 2.f*v.z; w.w = 2.f*v.w;
        if (m == nc)   w.x -= 1.f; if (m == nc+1) w.y -= 1.f;
        if (m == nc+2) w.z -= 1.f; if (m == nc+3) w.w -= 1.f;
        ((float4*)C2)[q] = w;
    }
}

__global__ void k_stepcomb(const float* __restrict__ Qs, const float* __restrict__ QU,
                           float* __restrict__ Psq, float* __restrict__ Unext, int rows) {
    int q = blockIdx.x*blockDim.x + threadIdx.x;
    const size_t SZ = (size_t)Nh*Nh/4;
    if (q < (int)SZ) {
        ((float4*)Psq)[q] = sum4((const float4*)Qs, (size_t)q, SZ);
    } else {
        int qq = q - (int)SZ;
        if ((qq >> 8) < rows) {
            const size_t SU = (size_t)256*Nh/4;
            ((float4*)Unext)[qq] = sum4((const float4*)QU, (size_t)qq, SU);
        }
    }
}

// ---------------- matvec: y = Mat @ x, optional scale exp(logd) ----------------
__global__ void k_matvec(const float* __restrict__ Mat, const float* __restrict__ x,
                         float* __restrict__ y, const float* __restrict__ logd) {
    int gw   = (blockIdx.x*blockDim.x + threadIdx.x) >> 5;
    int lane = threadIdx.x & 31;
    if (gw >= Nh) return;
    const float4* r  = (const float4*)(Mat + (size_t)gw*Nh);
    const float4* xv = (const float4*)x;
    float acc = 0.f;
    #pragma unroll 4
    for (int j = lane; j < Nh/4; j += 32) {
        float4 a = r[j], b = xv[j];
        acc += a.x*b.x + a.y*b.y + a.z*b.z + a.w*b.w;
    }
    #pragma unroll
    for (int o = 16; o; o >>= 1) acc += __shfl_down_sync(0xffffffffu, acc, o);
    if (lane == 0) {
        float s = 1.f;
        if (logd) s = (float)exp((double)logd[0]);
        y[gw] = s*acc;
    }
}

// ---------------- K[t1 + 512*t2] = dot(U[t1,:], W[t2,:]) ----------------
__global__ void k_gk(const float* __restrict__ U, const float* __restrict__ W,
                     float* __restrict__ K) {
    int gw   = (blockIdx.x*blockDim.x + threadIdx.x) >> 5;
    int lane = threadIdx.x & 31;
    if (gw >= LSEQ) return;
    int t1 = gw & (NT1 - 1);
    int t2 = gw >> 9;
    const float4* u = (const float4*)(U + (size_t)t1*Nh);
    const float4* w = (const float4*)(W + (size_t)t2*Nh);
    float acc = 0.f;
    #pragma unroll 4
    for (int j = lane; j < Nh/4; j += 32) {
        float4 a = u[j], b = w[j];
        acc += a.x*b.x + a.y*b.y + a.z*b.z + a.w*b.w;
    }
    #pragma unroll
    for (int o = 16; o; o >>= 1) acc += __shfl_down_sync(0xffffffffu, acc, o);
    if (lane == 0) K[gw] = acc;
}

// ---------------- causal conv: Y[k] = sum_{t<=k} K[t] X[k-t] + D*X[k] ----------------
__global__ __launch_bounds__(128)
void k_conv(const float* __restrict__ X, const float* __restrict__ K,
            const float* __restrict__ D, float* __restrict__ Y) {
    __shared__ float Ks[256];
    __shared__ float Xs[128];
    const int i  = blockIdx.x;
    const int kk = threadIdx.x;
    float acc = 0.f;
    for (int j = 0; j <= i; j++) {
        int base = (i - j) << 7;
        __syncthreads();
        Xs[kk] = X[(j << 7) + kk];
        int i0 = base - 128 + kk;
        Ks[kk]       = (i0 >= 0) ? K[i0] : 0.f;
        Ks[kk + 128] = K[base + kk];
        __syncthreads();
        #pragma unroll 8
        for (int t = 0; t < 128; t++)
            acc += Ks[kk + 128 - t] * Xs[t];
    }
    int k = (i << 7) + kk;
    Y[k] = acc + D[0]*X[k];
}

// ---------------- host ----------------
extern "C" void kernel_launch(void* const* d_in, const int* in_sizes, int n_in,
                              void* d_out, int out_size) {
    int iX=-1, iA=-1, iB=-1, iC=-1, iD=-1, iLd=-1;
    for (int i = 0; i < n_in; i++) {
        int s = in_sizes[i];
        if      (s == Nh*Nh) iA = i;
        else if (s == LSEQ)  iX = i;
        else if (s == Nh)    { if (iB < 0) iB = i; else iC = i; }
        else if (s == 1)     { if (iD < 0) iD = i; else iLd = i; }
    }
    const float* X    = (const float*)d_in[iX];
    const float* A    = (const float*)d_in[iA];
    const float* Bv   = (const float*)d_in[iB];
    const float* Cv   = (const float*)d_in[iC];
    const float* Dv   = (const float*)d_in[iD];
    const float* logd = (const float*)d_in[iLd];
    float* Y = (float*)d_out;
    (void)out_size;

    float *pS, *pT, *pP, *pM, *pU, *pW, *pK, *pQ, *pQU;
    cudaGetSymbolAddress((void**)&pS, g_S);
    cudaGetSymbolAddress((void**)&pT, g_T);
    cudaGetSymbolAddress((void**)&pP, g_P);
    cudaGetSymbolAddress((void**)&pM, g_M);
    cudaGetSymbolAddress((void**)&pU, g_U);
    cudaGetSymbolAddress((void**)&pW, g_W);
    cudaGetSymbolAddress((void**)&pK, g_K);
    cudaGetSymbolAddress((void**)&pQ, g_Q);
    cudaGetSymbolAddress((void**)&pQU, g_QU);

    const int EW = (Nh*Nh)/256;
    dim3 gp(Nh/BN, Nh/BM, KS);   // 16 x 8 x 4 = 512 CTAs
    const int CB = (Nh*Nh/4)/256;  // 1024 combine blocks

    // S = (d/2) A   -> g_S
    k_prep<<<EW, 256>>>(A, logd, pS);
    // P0 = I + S + S^2                      -> g_P
    k_gemm_part<<<gp, NTHR>>>(pS, pS, pQ, Nh);
    k_comb<MODE_P0><<<CB, 256>>>(pQ, pS, pP, nullptr);
    // R  = 2I - P0 + S@P0                   -> g_T
    k_gemm_part<<<gp, NTHR>>>(pS, pP, pQ, Nh);
    k_comb<MODE_R ><<<CB, 256>>>(pQ, pP, pT, nullptr);
    // P  = P0@R -> g_S ;  M = 2P - I -> g_M
    k_gemm_part<<<gp, NTHR>>>(pP, pT, pQ, Nh);
    k_comb<MODE_PM><<<CB, 256>>>(pQ, nullptr, pS, pM);

    k_matvec<<<128, 256>>>(pS, Bv, pW, logd);      // W[0] = dB = d * P @ B
    k_copy<<<4, 256>>>(Cv, pU, Nh);                // U[0] = c

    // Fused doubling: U[rows..2rows) = U @ M^{2^s}, M^{2^{s+1}} = (M^{2^s})^2
    float* pw   = pM;
    float* ping = pP;
    float* pong = pT;
    int rows = 1;
    for (int s = 0; s < 9; s++) {
        int urt = (rows + BM - 1)/BM;          // 1 (rows<=128) or 2 (rows=256)
        dim3 gs(Nh/BN, 8 + urt, KS);
        k_step_part<<<gs, NTHR>>>(pU, pw, rows, pQ, pQU);
        int totq = Nh*Nh/4 + rows*(Nh/4);
        k_stepcomb<<<(totq + 255)/256, 256>>>(pQ, pQU, ping, pU + (size_t)rows*Nh, rows);
        pw = ping;
        float* tmp = ping; ping = pong; pong = tmp;
        rows <<= 1;
    }
    // pw = M^512

    // W[t] = M^512 @ W[t-1], t = 1..31
    for (int t = 1; t < NT2; t++)
        k_matvec<<<128, 256>>>(pw, pW + (size_t)(t-1)*Nh, pW + (size_t)t*Nh, nullptr);

    // K[t1 + 512*t2] = U[t1] . W[t2]
    k_gk<<<LSEQ/8, 256>>>(pU, pW, pK);

    // y = K (*) X + D*X
    k_conv<<<LSEQ/128, 128>>>(X, pK, Dv, Y);
}